// round 9
// baseline (speedup 1.0000x reference)
#include <cuda_runtime.h>
#include <cstdint>

#define NN      50000
#define EE      800000
#define ET      (EE + NN)
#define IN_DIM  256
#define HID     32
#define HEADS   4
#define OUT_DIM 40
#define F1      128
#define F2      160
#define SLOPE   0.2f
#define FULLMASK 0xffffffffu

// ---------------- scratch ----------------
__device__ float g_xc1[(size_t)NN * 256];   // [xl1 | xr1]
__device__ float g_xc2[(size_t)NN * 320];   // [xl2 | xr2]
__device__ float g_h  [(size_t)NN * F1];
__device__ int   g_deg[NN];
__device__ int   g_rowptr[NN + 1];
__device__ int   g_cursor[NN];
__device__ int   g_csrsrc[ET];
__device__ int   g_work1;
__device__ int   g_work2;

// ---------------- CSR build ----------------
__global__ void count_kernel(const int* __restrict__ edst)
{
    int idx = blockIdx.x * blockDim.x + threadIdx.x;
    if (idx >= ET) return;
    int d = (idx < EE) ? edst[idx] : idx - EE;
    atomicAdd(&g_deg[d], 1);
}

__global__ void scan_kernel()
{
    __shared__ int ssum[1024];
    int t = threadIdx.x;
    const int CH = (NN + 1023) / 1024;
    int lo = t * CH;
    int hi = min(lo + CH, NN);
    int s = 0;
    for (int i = lo; i < hi; i++) s += g_deg[i];
    ssum[t] = s;
    __syncthreads();
    for (int off = 1; off < 1024; off <<= 1) {
        int v = (t >= off) ? ssum[t - off] : 0;
        __syncthreads();
        ssum[t] += v;
        __syncthreads();
    }
    int base = (t == 0) ? 0 : ssum[t - 1];
    for (int i = lo; i < hi; i++) {
        g_rowptr[i] = base;
        g_cursor[i] = base;
        base += g_deg[i];
    }
    if (t == 0) g_rowptr[NN] = ET;
}

__global__ void scatter_kernel(const int* __restrict__ esrc, const int* __restrict__ edst)
{
    int idx = blockIdx.x * blockDim.x + threadIdx.x;
    if (idx >= ET) return;
    int s, d;
    if (idx < EE) { s = esrc[idx]; d = edst[idx]; }
    else          { s = d = idx - EE; }
    int pos = atomicAdd(&g_cursor[d], 1);
    g_csrsrc[pos] = s;
}

// ---------------- helpers ----------------
__device__ __forceinline__ uint32_t f2tf(float f) {
    uint32_t r;
    asm("cvt.rna.tf32.f32 %0, %1;" : "=r"(r) : "f"(f));
    return r;
}
__device__ __forceinline__ void cpa16(uint32_t d, const void* s, int sz) {
    asm volatile("cp.async.cg.shared.global [%0], [%1], 16, %2;"
                 :: "r"(d), "l"(s), "r"(sz));
}

// ---------------- TF32 GEMM, cp.async double-buffered, fused concat+bias ----------------
// C[M, 2*Nh] = A[M,K] @ [Wl | Wr] + [bl | br]
__global__ __launch_bounds__(256, 2) void gemm_tf32_fused(
    const float* __restrict__ A, const float* __restrict__ Wl,
    const float* __restrict__ Wr, const float* __restrict__ bl,
    const float* __restrict__ br, float* __restrict__ C,
    int M, int K, int Nh)
{
    const int N = 2 * Nh;
    __shared__ uint32_t As[2][16][136];
    __shared__ float    Bs[2][16][136];
    int tid = threadIdx.x, lane = tid & 31, warp = tid >> 5;
    int wm = warp & 3, wn = warp >> 2;
    int rowBase = blockIdx.y * 128, colBase = blockIdx.x * 128;
    int grp = lane >> 2, tig = lane & 3;

    float acc[2][8][4];
    #pragma unroll
    for (int mt = 0; mt < 2; mt++)
        #pragma unroll
        for (int nt = 0; nt < 8; nt++)
            #pragma unroll
            for (int c = 0; c < 4; c++) acc[mt][nt][c] = 0.f;

    int nIter = K >> 4;

    float4 pa, pb;
    {
        int gr = rowBase + (tid >> 1);
        int kc = (tid & 1) * 8;
        pa = make_float4(0.f, 0.f, 0.f, 0.f); pb = pa;
        if (gr < M) {
            pa = *(const float4*)(A + (size_t)gr * K + kc);
            pb = *(const float4*)(A + (size_t)gr * K + kc + 4);
        }
    }
    {
        int rB = tid >> 4;
        int cB = (tid & 15) * 8;
        #pragma unroll
        for (int i = 0; i < 2; i++) {
            int gc = colBase + cB + i * 4;
            const float* src = Wl; int sz = 0;
            if (gc < Nh)      { src = Wl + (size_t)rB * Nh + gc;        sz = 16; }
            else if (gc < N)  { src = Wr + (size_t)rB * Nh + (gc - Nh); sz = 16; }
            cpa16((uint32_t)__cvta_generic_to_shared(&Bs[0][rB][cB + i * 4]), src, sz);
        }
    }
    {
        int r = tid >> 1, c4 = (tid & 1) * 8;
        As[0][c4 + 0][r] = f2tf(pa.x); As[0][c4 + 1][r] = f2tf(pa.y);
        As[0][c4 + 2][r] = f2tf(pa.z); As[0][c4 + 3][r] = f2tf(pa.w);
        As[0][c4 + 4][r] = f2tf(pb.x); As[0][c4 + 5][r] = f2tf(pb.y);
        As[0][c4 + 6][r] = f2tf(pb.z); As[0][c4 + 7][r] = f2tf(pb.w);
    }
    asm volatile("cp.async.commit_group;");

    int buf = 0;
    for (int it = 0; it < nIter; it++) {
        asm volatile("cp.async.wait_group 0;");
        __syncthreads();
        bool more = (it + 1 < nIter);
        if (more) {
            int k0 = (it + 1) << 4;
            int gr = rowBase + (tid >> 1);
            int kc = k0 + (tid & 1) * 8;
            pa = make_float4(0.f, 0.f, 0.f, 0.f); pb = pa;
            if (gr < M) {
                pa = *(const float4*)(A + (size_t)gr * K + kc);
                pb = *(const float4*)(A + (size_t)gr * K + kc + 4);
            }
            int rB = tid >> 4;
            int cB = (tid & 15) * 8;
            #pragma unroll
            for (int i = 0; i < 2; i++) {
                int gc = colBase + cB + i * 4;
                const float* src = Wl; int sz = 0;
                if (gc < Nh)      { src = Wl + (size_t)(k0 + rB) * Nh + gc;        sz = 16; }
                else if (gc < N)  { src = Wr + (size_t)(k0 + rB) * Nh + (gc - Nh); sz = 16; }
                cpa16((uint32_t)__cvta_generic_to_shared(&Bs[buf ^ 1][rB][cB + i * 4]), src, sz);
            }
            asm volatile("cp.async.commit_group;");
        }

        #pragma unroll
        for (int ks = 0; ks < 16; ks += 8) {
            uint32_t af[2][4], bf[8][2];
            #pragma unroll
            for (int mt = 0; mt < 2; mt++) {
                int m = wm * 32 + mt * 16;
                af[mt][0] = As[buf][ks + tig][m + grp];
                af[mt][1] = As[buf][ks + tig][m + grp + 8];
                af[mt][2] = As[buf][ks + tig + 4][m + grp];
                af[mt][3] = As[buf][ks + tig + 4][m + grp + 8];
            }
            #pragma unroll
            for (int nt = 0; nt < 8; nt++) {
                int nb = wn * 64 + nt * 8;
                bf[nt][0] = f2tf(Bs[buf][ks + tig][nb + grp]);
                bf[nt][1] = f2tf(Bs[buf][ks + tig + 4][nb + grp]);
            }
            #pragma unroll
            for (int mt = 0; mt < 2; mt++)
                #pragma unroll
                for (int nt = 0; nt < 8; nt++) {
                    asm volatile(
                        "mma.sync.aligned.m16n8k8.row.col.f32.tf32.tf32.f32 "
                        "{%0,%1,%2,%3}, {%4,%5,%6,%7}, {%8,%9}, {%0,%1,%2,%3};"
                        : "+f"(acc[mt][nt][0]), "+f"(acc[mt][nt][1]),
                          "+f"(acc[mt][nt][2]), "+f"(acc[mt][nt][3])
                        : "r"(af[mt][0]), "r"(af[mt][1]), "r"(af[mt][2]), "r"(af[mt][3]),
                          "r"(bf[nt][0]), "r"(bf[nt][1]));
                }
        }

        if (more) {
            int r = tid >> 1, c4 = (tid & 1) * 8;
            int b = buf ^ 1;
            As[b][c4 + 0][r] = f2tf(pa.x); As[b][c4 + 1][r] = f2tf(pa.y);
            As[b][c4 + 2][r] = f2tf(pa.z); As[b][c4 + 3][r] = f2tf(pa.w);
            As[b][c4 + 4][r] = f2tf(pb.x); As[b][c4 + 5][r] = f2tf(pb.y);
            As[b][c4 + 6][r] = f2tf(pb.z); As[b][c4 + 7][r] = f2tf(pb.w);
        }
        buf ^= 1;
    }

    #pragma unroll
    for (int mt = 0; mt < 2; mt++) {
        #pragma unroll
        for (int nt = 0; nt < 8; nt++) {
            int row0 = rowBase + wm * 32 + mt * 16 + grp;
            int col0 = colBase + wn * 64 + nt * 8 + tig * 2;
            if (col0 < N) {
                float b0 = (col0     < Nh) ? bl[col0]     : br[col0 - Nh];
                float b1 = (col0 + 1 < Nh) ? bl[col0 + 1] : br[col0 + 1 - Nh];
                if (row0 < M) {
                    float2 o = make_float2(acc[mt][nt][0] + b0, acc[mt][nt][1] + b1);
                    *(float2*)(C + (size_t)row0 * N + col0) = o;
                }
                if (row0 + 8 < M) {
                    float2 o = make_float2(acc[mt][nt][2] + b0, acc[mt][nt][3] + b1);
                    *(float2*)(C + (size_t)(row0 + 8) * N + col0) = o;
                }
            }
        }
    }
}

// ---------------- layer 1 agg: persistent warps, half-warp/edge, depth-2 prefetch ----------------
__global__ __launch_bounds__(256) void agg1_kernel(
    const float* __restrict__ xc, const int* __restrict__ rowptr,
    const int* __restrict__ csrsrc, const float* __restrict__ att,
    const float* __restrict__ bias, float* __restrict__ hout)
{
    int lane = threadIdx.x & 31;
    int sub = lane >> 4, l = lane & 15;

    float4 va0 = *(const float4*)(att + l * 8);
    float4 va1 = *(const float4*)(att + l * 8 + 4);
    float4 b0v = *(const float4*)(bias + l * 8);
    float4 b1v = *(const float4*)(bias + l * 8 + 4);

    for (;;) {
        int node;
        if (lane == 0) node = atomicAdd(&g_work1, 1);
        node = __shfl_sync(FULLMASK, node, 0);
        if (node >= NN) break;

        const float* vp = xc + (size_t)node * 256 + 128 + l * 8;
        float4 vr0 = *(const float4*)(vp);
        float4 vr1 = *(const float4*)(vp + 4);

        int beg = rowptr[node], end = rowptr[node + 1];
        int iters = (end - beg + 1) >> 1;

        float4 acc0 = make_float4(0.f, 0.f, 0.f, 0.f);
        float4 acc1 = make_float4(0.f, 0.f, 0.f, 0.f);
        float ssum = 0.f;

        int idx = beg + sub;
        bool v = idx < end;
        int s = v ? csrsrc[idx] : csrsrc[beg];
        const float* sp = xc + (size_t)s * 256 + l * 8;
        float4 c0 = *(const float4*)sp;
        float4 c1 = *(const float4*)(sp + 4);

        for (int it = 0; it < iters; it++) {
            int idxn = idx + 2;
            bool vn = idxn < end;
            int sn = vn ? csrsrc[idxn] : csrsrc[beg];
            const float* np = xc + (size_t)sn * 256 + l * 8;
            float4 n0 = *(const float4*)np;
            float4 n1 = *(const float4*)(np + 4);

            float g, sum = 0.f;
            g = c0.x + vr0.x; g = g > 0.f ? g : SLOPE * g; sum += g * va0.x;
            g = c0.y + vr0.y; g = g > 0.f ? g : SLOPE * g; sum += g * va0.y;
            g = c0.z + vr0.z; g = g > 0.f ? g : SLOPE * g; sum += g * va0.z;
            g = c0.w + vr0.w; g = g > 0.f ? g : SLOPE * g; sum += g * va0.w;
            g = c1.x + vr1.x; g = g > 0.f ? g : SLOPE * g; sum += g * va1.x;
            g = c1.y + vr1.y; g = g > 0.f ? g : SLOPE * g; sum += g * va1.y;
            g = c1.z + vr1.z; g = g > 0.f ? g : SLOPE * g; sum += g * va1.z;
            g = c1.w + vr1.w; g = g > 0.f ? g : SLOPE * g; sum += g * va1.w;
            sum += __shfl_xor_sync(FULLMASK, sum, 1);
            sum += __shfl_xor_sync(FULLMASK, sum, 2);
            float a = v ? __expf(sum) : 0.f;
            acc0.x += a * c0.x; acc0.y += a * c0.y; acc0.z += a * c0.z; acc0.w += a * c0.w;
            acc1.x += a * c1.x; acc1.y += a * c1.y; acc1.z += a * c1.z; acc1.w += a * c1.w;
            ssum += a;
            c0 = n0; c1 = n1; v = vn; idx = idxn;
        }

        acc0.x += __shfl_xor_sync(FULLMASK, acc0.x, 16);
        acc0.y += __shfl_xor_sync(FULLMASK, acc0.y, 16);
        acc0.z += __shfl_xor_sync(FULLMASK, acc0.z, 16);
        acc0.w += __shfl_xor_sync(FULLMASK, acc0.w, 16);
        acc1.x += __shfl_xor_sync(FULLMASK, acc1.x, 16);
        acc1.y += __shfl_xor_sync(FULLMASK, acc1.y, 16);
        acc1.z += __shfl_xor_sync(FULLMASK, acc1.z, 16);
        acc1.w += __shfl_xor_sync(FULLMASK, acc1.w, 16);
        ssum   += __shfl_xor_sync(FULLMASK, ssum,   16);

        if (sub == 0) {
            float inv = 1.f / (ssum + 1e-16f);
            float4 o0, o1;
            o0.x = acc0.x * inv + b0v.x; o0.y = acc0.y * inv + b0v.y;
            o0.z = acc0.z * inv + b0v.z; o0.w = acc0.w * inv + b0v.w;
            o1.x = acc1.x * inv + b1v.x; o1.y = acc1.y * inv + b1v.y;
            o1.z = acc1.z * inv + b1v.z; o1.w = acc1.w * inv + b1v.w;
            o0.x = o0.x > 0.f ? o0.x : (__expf(o0.x) - 1.f);
            o0.y = o0.y > 0.f ? o0.y : (__expf(o0.y) - 1.f);
            o0.z = o0.z > 0.f ? o0.z : (__expf(o0.z) - 1.f);
            o0.w = o0.w > 0.f ? o0.w : (__expf(o0.w) - 1.f);
            o1.x = o1.x > 0.f ? o1.x : (__expf(o1.x) - 1.f);
            o1.y = o1.y > 0.f ? o1.y : (__expf(o1.y) - 1.f);
            o1.z = o1.z > 0.f ? o1.z : (__expf(o1.z) - 1.f);
            o1.w = o1.w > 0.f ? o1.w : (__expf(o1.w) - 1.f);
            *(float4*)(hout + (size_t)node * F1 + l * 8)     = o0;
            *(float4*)(hout + (size_t)node * F1 + l * 8 + 4) = o1;
        }
    }
}

// ---------------- layer 2 agg: persistent warps, half-warp/edge, depth-2 prefetch ----------------
__global__ __launch_bounds__(256) void agg2_kernel(
    const float* __restrict__ xc, const int* __restrict__ rowptr,
    const int* __restrict__ csrsrc, const float* __restrict__ att,
    const float* __restrict__ bias, float* __restrict__ out)
{
    int lane = threadIdx.x & 31;
    int sub = lane >> 4, l = lane & 15;
    int base = l * 10;   // head = l>>2

    float2 va[5];
    #pragma unroll
    for (int j = 0; j < 5; j++)
        va[j] = *(const float2*)(att + base + 2 * j);

    for (;;) {
        int node;
        if (lane == 0) node = atomicAdd(&g_work2, 1);
        node = __shfl_sync(FULLMASK, node, 0);
        if (node >= NN) break;

        float2 vr[5];
        const float* vp = xc + (size_t)node * 320 + 160 + base;
        #pragma unroll
        for (int j = 0; j < 5; j++)
            vr[j] = *(const float2*)(vp + 2 * j);

        int beg = rowptr[node], end = rowptr[node + 1];
        int iters = (end - beg + 1) >> 1;

        float2 acc[5];
        #pragma unroll
        for (int j = 0; j < 5; j++) acc[j] = make_float2(0.f, 0.f);
        float ssum = 0.f;

        int idx = beg + sub;
        bool v = idx < end;
        int s = v ? csrsrc[idx] : csrsrc[beg];
        float2 cur[5];
        {
            const float* sp = xc + (size_t)s * 320 + base;
            #pragma unroll
            for (int j = 0; j < 5; j++) cur[j] = *(const float2*)(sp + 2 * j);
        }

        for (int it = 0; it < iters; it++) {
            int idxn = idx + 2;
            bool vn = idxn < end;
            int sn = vn ? csrsrc[idxn] : csrsrc[beg];
            float2 nxt[5];
            {
                const float* sp = xc + (size_t)sn * 320 + base;
                #pragma unroll
                for (int j = 0; j < 5; j++) nxt[j] = *(const float2*)(sp + 2 * j);
            }
            float sum = 0.f;
            #pragma unroll
            for (int j = 0; j < 5; j++) {
                float g = cur[j].x + vr[j].x; g = g > 0.f ? g : SLOPE * g; sum += g * va[j].x;
                g       = cur[j].y + vr[j].y; g = g > 0.f ? g : SLOPE * g; sum += g * va[j].y;
            }
            sum += __shfl_xor_sync(FULLMASK, sum, 1);
            sum += __shfl_xor_sync(FULLMASK, sum, 2);
            float a = v ? __expf(sum) : 0.f;
            #pragma unroll
            for (int j = 0; j < 5; j++) { acc[j].x += a * cur[j].x; acc[j].y += a * cur[j].y; }
            ssum += a;
            #pragma unroll
            for (int j = 0; j < 5; j++) cur[j] = nxt[j];
            v = vn; idx = idxn;
        }

        #pragma unroll
        for (int j = 0; j < 5; j++) {
            acc[j].x += __shfl_xor_sync(FULLMASK, acc[j].x, 16);
            acc[j].y += __shfl_xor_sync(FULLMASK, acc[j].y, 16);
        }
        ssum += __shfl_xor_sync(FULLMASK, ssum, 16);

        float inv = 1.f / (ssum + 1e-16f);
        #pragma unroll
        for (int j = 0; j < 5; j++) {
            float vx = acc[j].x * inv, vy = acc[j].y * inv;
            vx += __shfl_xor_sync(FULLMASK, vx, 4);
            vx += __shfl_xor_sync(FULLMASK, vx, 8);
            vy += __shfl_xor_sync(FULLMASK, vy, 4);
            vy += __shfl_xor_sync(FULLMASK, vy, 8);
            acc[j].x = vx; acc[j].y = vy;
        }

        if (sub == 0 && l < 4) {
            #pragma unroll
            for (int j = 0; j < 5; j++) {
                float2 o;
                o.x = 0.25f * acc[j].x + bias[base + 2 * j];
                o.y = 0.25f * acc[j].y + bias[base + 2 * j + 1];
                *(float2*)(out + (size_t)node * OUT_DIM + base + 2 * j) = o;
            }
        }
    }
}

// ---------------- host ----------------
struct Ptrs {
    float *xc1, *xc2, *h;
    int *deg, *rowptr, *csrsrc, *work1, *work2;
};
static Ptrs P;
static cudaStream_t g_s2;
static cudaEvent_t g_ev1, g_ev2;
static bool g_init = false;

extern "C" void kernel_launch(void* const* d_in, const int* in_sizes, int n_in,
                              void* d_out, int out_size)
{
    if (!g_init) {
        cudaGetSymbolAddress((void**)&P.xc1,    g_xc1);
        cudaGetSymbolAddress((void**)&P.xc2,    g_xc2);
        cudaGetSymbolAddress((void**)&P.h,      g_h);
        cudaGetSymbolAddress((void**)&P.deg,    g_deg);
        cudaGetSymbolAddress((void**)&P.rowptr, g_rowptr);
        cudaGetSymbolAddress((void**)&P.csrsrc, g_csrsrc);
        cudaGetSymbolAddress((void**)&P.work1,  g_work1);
        cudaGetSymbolAddress((void**)&P.work2,  g_work2);
        cudaStreamCreateWithFlags(&g_s2, cudaStreamNonBlocking);
        cudaEventCreateWithFlags(&g_ev1, cudaEventDisableTiming);
        cudaEventCreateWithFlags(&g_ev2, cudaEventDisableTiming);
        g_init = true;
    }

    const float* x     = (const float*)d_in[0];
    const int*   ei    = (const int*)  d_in[1];
    const float* Wl1   = (const float*)d_in[2];
    const float* bl1   = (const float*)d_in[3];
    const float* Wr1   = (const float*)d_in[4];
    const float* br1   = (const float*)d_in[5];
    const float* att1  = (const float*)d_in[6];
    const float* bias1 = (const float*)d_in[7];
    const float* Wl2   = (const float*)d_in[8];
    const float* bl2   = (const float*)d_in[9];
    const float* Wr2   = (const float*)d_in[10];
    const float* br2   = (const float*)d_in[11];
    const float* att2  = (const float*)d_in[12];
    const float* bias2 = (const float*)d_in[13];
    float* out = (float*)d_out;

    const int* esrc = ei;
    const int* edst = ei + EE;

    // zero work counters (main stream, before aggs)
    cudaMemsetAsync(P.work1, 0, sizeof(int));
    cudaMemsetAsync(P.work2, 0, sizeof(int));

    // fork: CSR build on side stream, concurrent with GEMM1
    cudaEventRecord(g_ev1, 0);
    cudaStreamWaitEvent(g_s2, g_ev1, 0);
    cudaMemsetAsync(P.deg, 0, NN * sizeof(int), g_s2);
    count_kernel<<<(ET + 255) / 256, 256, 0, g_s2>>>(edst);
    scan_kernel<<<1, 1024, 0, g_s2>>>();
    scatter_kernel<<<(ET + 255) / 256, 256, 0, g_s2>>>(esrc, edst);
    cudaEventRecord(g_ev2, g_s2);

    // ----- layer 1 GEMM (main stream) -----
    {
        dim3 grid(2, (NN + 127) / 128);
        gemm_tf32_fused<<<grid, 256>>>(x, Wl1, Wr1, bl1, br1, P.xc1, NN, IN_DIM, F1);
    }
    cudaStreamWaitEvent(0, g_ev2, 0);
    agg1_kernel<<<1536, 256>>>(P.xc1, P.rowptr, P.csrsrc, att1, bias1, P.h);

    // ----- layer 2 -----
    {
        dim3 grid(3, (NN + 127) / 128);
        gemm_tf32_fused<<<grid, 256>>>(P.h, Wl2, Wr2, bl2, br2, P.xc2, NN, F1, F2);
    }
    agg2_kernel<<<1536, 256>>>(P.xc2, P.rowptr, P.csrsrc, att2, bias2, out);
}

// round 10
// speedup vs baseline: 1.0114x; 1.0114x over previous
#include <cuda_runtime.h>
#include <cstdint>

#define NN      50000
#define EE      800000
#define ET      (EE + NN)
#define IN_DIM  256
#define HID     32
#define HEADS   4
#define OUT_DIM 40
#define F1      128
#define F2      160
#define SLOPE   0.2f
#define FULLMASK 0xffffffffu
#define NCHUNK  4
#define CHSZ    12500        // NN / NCHUNK

// ---------------- scratch ----------------
__device__ float g_xc1[(size_t)NN * 256];   // [xl1 | xr1]
__device__ float g_xc2[(size_t)NN * 320];   // [xl2 | xr2]
__device__ float g_h  [(size_t)NN * F1];
__device__ int   g_deg[NN];
__device__ int   g_rowptr[NN + 1];
__device__ int   g_cursor[NN];
__device__ int   g_csrsrc[ET];

// ---------------- CSR build ----------------
__global__ void count_kernel(const int* __restrict__ edst)
{
    int idx = blockIdx.x * blockDim.x + threadIdx.x;
    if (idx >= ET) return;
    int d = (idx < EE) ? edst[idx] : idx - EE;
    atomicAdd(&g_deg[d], 1);
}

__global__ void scan_kernel()
{
    __shared__ int ssum[1024];
    int t = threadIdx.x;
    const int CH = (NN + 1023) / 1024;
    int lo = t * CH;
    int hi = min(lo + CH, NN);
    int s = 0;
    for (int i = lo; i < hi; i++) s += g_deg[i];
    ssum[t] = s;
    __syncthreads();
    for (int off = 1; off < 1024; off <<= 1) {
        int v = (t >= off) ? ssum[t - off] : 0;
        __syncthreads();
        ssum[t] += v;
        __syncthreads();
    }
    int base = (t == 0) ? 0 : ssum[t - 1];
    for (int i = lo; i < hi; i++) {
        g_rowptr[i] = base;
        g_cursor[i] = base;
        base += g_deg[i];
    }
    if (t == 0) g_rowptr[NN] = ET;
}

__global__ void scatter_kernel(const int* __restrict__ esrc, const int* __restrict__ edst)
{
    int idx = blockIdx.x * blockDim.x + threadIdx.x;
    if (idx >= ET) return;
    int s, d;
    if (idx < EE) { s = esrc[idx]; d = edst[idx]; }
    else          { s = d = idx - EE; }
    int pos = atomicAdd(&g_cursor[d], 1);
    g_csrsrc[pos] = s;
}

// ---------------- helpers ----------------
__device__ __forceinline__ uint32_t f2tf(float f) {
    uint32_t r;
    asm("cvt.rna.tf32.f32 %0, %1;" : "=r"(r) : "f"(f));
    return r;
}
__device__ __forceinline__ void cpa16(uint32_t d, const void* s, int sz) {
    asm volatile("cp.async.cg.shared.global [%0], [%1], 16, %2;"
                 :: "r"(d), "l"(s), "r"(sz));
}

// ---------------- TF32 GEMM, cp.async double-buffered, fused concat+bias ----------------
// C[rowLo + 128*by .., 2*Nh] = A @ [Wl | Wr] + [bl | br]
__global__ __launch_bounds__(256, 2) void gemm_tf32_fused(
    const float* __restrict__ A, const float* __restrict__ Wl,
    const float* __restrict__ Wr, const float* __restrict__ bl,
    const float* __restrict__ br, float* __restrict__ C,
    int M, int K, int Nh, int rowLo)
{
    const int N = 2 * Nh;
    __shared__ uint32_t As[2][16][136];
    __shared__ float    Bs[2][16][136];
    int tid = threadIdx.x, lane = tid & 31, warp = tid >> 5;
    int wm = warp & 3, wn = warp >> 2;
    int rowBase = rowLo + blockIdx.y * 128, colBase = blockIdx.x * 128;
    int grp = lane >> 2, tig = lane & 3;

    float acc[2][8][4];
    #pragma unroll
    for (int mt = 0; mt < 2; mt++)
        #pragma unroll
        for (int nt = 0; nt < 8; nt++)
            #pragma unroll
            for (int c = 0; c < 4; c++) acc[mt][nt][c] = 0.f;

    int nIter = K >> 4;

    float4 pa, pb;
    {
        int gr = rowBase + (tid >> 1);
        int kc = (tid & 1) * 8;
        pa = make_float4(0.f, 0.f, 0.f, 0.f); pb = pa;
        if (gr < M) {
            pa = *(const float4*)(A + (size_t)gr * K + kc);
            pb = *(const float4*)(A + (size_t)gr * K + kc + 4);
        }
    }
    {
        int rB = tid >> 4;
        int cB = (tid & 15) * 8;
        #pragma unroll
        for (int i = 0; i < 2; i++) {
            int gc = colBase + cB + i * 4;
            const float* src = Wl; int sz = 0;
            if (gc < Nh)      { src = Wl + (size_t)rB * Nh + gc;        sz = 16; }
            else if (gc < N)  { src = Wr + (size_t)rB * Nh + (gc - Nh); sz = 16; }
            cpa16((uint32_t)__cvta_generic_to_shared(&Bs[0][rB][cB + i * 4]), src, sz);
        }
    }
    {
        int r = tid >> 1, c4 = (tid & 1) * 8;
        As[0][c4 + 0][r] = f2tf(pa.x); As[0][c4 + 1][r] = f2tf(pa.y);
        As[0][c4 + 2][r] = f2tf(pa.z); As[0][c4 + 3][r] = f2tf(pa.w);
        As[0][c4 + 4][r] = f2tf(pb.x); As[0][c4 + 5][r] = f2tf(pb.y);
        As[0][c4 + 6][r] = f2tf(pb.z); As[0][c4 + 7][r] = f2tf(pb.w);
    }
    asm volatile("cp.async.commit_group;");

    int buf = 0;
    for (int it = 0; it < nIter; it++) {
        asm volatile("cp.async.wait_group 0;");
        __syncthreads();
        bool more = (it + 1 < nIter);
        if (more) {
            int k0 = (it + 1) << 4;
            int gr = rowBase + (tid >> 1);
            int kc = k0 + (tid & 1) * 8;
            pa = make_float4(0.f, 0.f, 0.f, 0.f); pb = pa;
            if (gr < M) {
                pa = *(const float4*)(A + (size_t)gr * K + kc);
                pb = *(const float4*)(A + (size_t)gr * K + kc + 4);
            }
            int rB = tid >> 4;
            int cB = (tid & 15) * 8;
            #pragma unroll
            for (int i = 0; i < 2; i++) {
                int gc = colBase + cB + i * 4;
                const float* src = Wl; int sz = 0;
                if (gc < Nh)      { src = Wl + (size_t)(k0 + rB) * Nh + gc;        sz = 16; }
                else if (gc < N)  { src = Wr + (size_t)(k0 + rB) * Nh + (gc - Nh); sz = 16; }
                cpa16((uint32_t)__cvta_generic_to_shared(&Bs[buf ^ 1][rB][cB + i * 4]), src, sz);
            }
            asm volatile("cp.async.commit_group;");
        }

        #pragma unroll
        for (int ks = 0; ks < 16; ks += 8) {
            uint32_t af[2][4], bf[8][2];
            #pragma unroll
            for (int mt = 0; mt < 2; mt++) {
                int m = wm * 32 + mt * 16;
                af[mt][0] = As[buf][ks + tig][m + grp];
                af[mt][1] = As[buf][ks + tig][m + grp + 8];
                af[mt][2] = As[buf][ks + tig + 4][m + grp];
                af[mt][3] = As[buf][ks + tig + 4][m + grp + 8];
            }
            #pragma unroll
            for (int nt = 0; nt < 8; nt++) {
                int nb = wn * 64 + nt * 8;
                bf[nt][0] = f2tf(Bs[buf][ks + tig][nb + grp]);
                bf[nt][1] = f2tf(Bs[buf][ks + tig + 4][nb + grp]);
            }
            #pragma unroll
            for (int mt = 0; mt < 2; mt++)
                #pragma unroll
                for (int nt = 0; nt < 8; nt++) {
                    asm volatile(
                        "mma.sync.aligned.m16n8k8.row.col.f32.tf32.tf32.f32 "
                        "{%0,%1,%2,%3}, {%4,%5,%6,%7}, {%8,%9}, {%0,%1,%2,%3};"
                        : "+f"(acc[mt][nt][0]), "+f"(acc[mt][nt][1]),
                          "+f"(acc[mt][nt][2]), "+f"(acc[mt][nt][3])
                        : "r"(af[mt][0]), "r"(af[mt][1]), "r"(af[mt][2]), "r"(af[mt][3]),
                          "r"(bf[nt][0]), "r"(bf[nt][1]));
                }
        }

        if (more) {
            int r = tid >> 1, c4 = (tid & 1) * 8;
            int b = buf ^ 1;
            As[b][c4 + 0][r] = f2tf(pa.x); As[b][c4 + 1][r] = f2tf(pa.y);
            As[b][c4 + 2][r] = f2tf(pa.z); As[b][c4 + 3][r] = f2tf(pa.w);
            As[b][c4 + 4][r] = f2tf(pb.x); As[b][c4 + 5][r] = f2tf(pb.y);
            As[b][c4 + 6][r] = f2tf(pb.z); As[b][c4 + 7][r] = f2tf(pb.w);
        }
        buf ^= 1;
    }

    #pragma unroll
    for (int mt = 0; mt < 2; mt++) {
        #pragma unroll
        for (int nt = 0; nt < 8; nt++) {
            int row0 = rowBase + wm * 32 + mt * 16 + grp;
            int col0 = colBase + wn * 64 + nt * 8 + tig * 2;
            if (col0 < N) {
                float b0 = (col0     < Nh) ? bl[col0]     : br[col0 - Nh];
                float b1 = (col0 + 1 < Nh) ? bl[col0 + 1] : br[col0 + 1 - Nh];
                if (row0 < M) {
                    float2 o = make_float2(acc[mt][nt][0] + b0, acc[mt][nt][1] + b1);
                    *(float2*)(C + (size_t)row0 * N + col0) = o;
                }
                if (row0 + 8 < M) {
                    float2 o = make_float2(acc[mt][nt][2] + b0, acc[mt][nt][3] + b1);
                    *(float2*)(C + (size_t)(row0 + 8) * N + col0) = o;
                }
            }
        }
    }
}

// ---------------- layer 1 agg: warp/node (range), half-warp/edge, depth-2 prefetch ----------------
__global__ __launch_bounds__(256) void agg1_kernel(
    const float* __restrict__ xc, const int* __restrict__ rowptr,
    const int* __restrict__ csrsrc, const float* __restrict__ att,
    const float* __restrict__ bias, float* __restrict__ hout,
    int nodeLo, int nodeHi)
{
    int node = nodeLo + ((blockIdx.x * blockDim.x + threadIdx.x) >> 5);
    int lane = threadIdx.x & 31;
    if (node >= nodeHi) return;
    int sub = lane >> 4, l = lane & 15;

    const float* vp = xc + (size_t)node * 256 + 128 + l * 8;
    float4 vr0 = *(const float4*)(vp);
    float4 vr1 = *(const float4*)(vp + 4);
    float4 va0 = *(const float4*)(att + l * 8);
    float4 va1 = *(const float4*)(att + l * 8 + 4);

    int beg = rowptr[node], end = rowptr[node + 1];
    int iters = (end - beg + 1) >> 1;

    float4 acc0 = make_float4(0.f, 0.f, 0.f, 0.f);
    float4 acc1 = make_float4(0.f, 0.f, 0.f, 0.f);
    float ssum = 0.f;

    int idx = beg + sub;
    bool v = idx < end;
    int s = v ? csrsrc[idx] : csrsrc[beg];
    const float* sp = xc + (size_t)s * 256 + l * 8;
    float4 c0 = *(const float4*)sp;
    float4 c1 = *(const float4*)(sp + 4);

    for (int it = 0; it < iters; it++) {
        int idxn = idx + 2;
        bool vn = idxn < end;
        int sn = vn ? csrsrc[idxn] : csrsrc[beg];
        const float* np = xc + (size_t)sn * 256 + l * 8;
        float4 n0 = *(const float4*)np;
        float4 n1 = *(const float4*)(np + 4);

        float g, sum = 0.f;
        g = c0.x + vr0.x; g = g > 0.f ? g : SLOPE * g; sum += g * va0.x;
        g = c0.y + vr0.y; g = g > 0.f ? g : SLOPE * g; sum += g * va0.y;
        g = c0.z + vr0.z; g = g > 0.f ? g : SLOPE * g; sum += g * va0.z;
        g = c0.w + vr0.w; g = g > 0.f ? g : SLOPE * g; sum += g * va0.w;
        g = c1.x + vr1.x; g = g > 0.f ? g : SLOPE * g; sum += g * va1.x;
        g = c1.y + vr1.y; g = g > 0.f ? g : SLOPE * g; sum += g * va1.y;
        g = c1.z + vr1.z; g = g > 0.f ? g : SLOPE * g; sum += g * va1.z;
        g = c1.w + vr1.w; g = g > 0.f ? g : SLOPE * g; sum += g * va1.w;
        sum += __shfl_xor_sync(FULLMASK, sum, 1);
        sum += __shfl_xor_sync(FULLMASK, sum, 2);
        float a = v ? __expf(sum) : 0.f;
        acc0.x += a * c0.x; acc0.y += a * c0.y; acc0.z += a * c0.z; acc0.w += a * c0.w;
        acc1.x += a * c1.x; acc1.y += a * c1.y; acc1.z += a * c1.z; acc1.w += a * c1.w;
        ssum += a;
        c0 = n0; c1 = n1; v = vn; idx = idxn;
    }

    acc0.x += __shfl_xor_sync(FULLMASK, acc0.x, 16);
    acc0.y += __shfl_xor_sync(FULLMASK, acc0.y, 16);
    acc0.z += __shfl_xor_sync(FULLMASK, acc0.z, 16);
    acc0.w += __shfl_xor_sync(FULLMASK, acc0.w, 16);
    acc1.x += __shfl_xor_sync(FULLMASK, acc1.x, 16);
    acc1.y += __shfl_xor_sync(FULLMASK, acc1.y, 16);
    acc1.z += __shfl_xor_sync(FULLMASK, acc1.z, 16);
    acc1.w += __shfl_xor_sync(FULLMASK, acc1.w, 16);
    ssum   += __shfl_xor_sync(FULLMASK, ssum,   16);

    if (sub == 0) {
        float inv = 1.f / (ssum + 1e-16f);
        float4 b0 = *(const float4*)(bias + l * 8);
        float4 b1 = *(const float4*)(bias + l * 8 + 4);
        float4 o0, o1;
        o0.x = acc0.x * inv + b0.x; o0.y = acc0.y * inv + b0.y;
        o0.z = acc0.z * inv + b0.z; o0.w = acc0.w * inv + b0.w;
        o1.x = acc1.x * inv + b1.x; o1.y = acc1.y * inv + b1.y;
        o1.z = acc1.z * inv + b1.z; o1.w = acc1.w * inv + b1.w;
        o0.x = o0.x > 0.f ? o0.x : (__expf(o0.x) - 1.f);
        o0.y = o0.y > 0.f ? o0.y : (__expf(o0.y) - 1.f);
        o0.z = o0.z > 0.f ? o0.z : (__expf(o0.z) - 1.f);
        o0.w = o0.w > 0.f ? o0.w : (__expf(o0.w) - 1.f);
        o1.x = o1.x > 0.f ? o1.x : (__expf(o1.x) - 1.f);
        o1.y = o1.y > 0.f ? o1.y : (__expf(o1.y) - 1.f);
        o1.z = o1.z > 0.f ? o1.z : (__expf(o1.z) - 1.f);
        o1.w = o1.w > 0.f ? o1.w : (__expf(o1.w) - 1.f);
        *(float4*)(hout + (size_t)node * F1 + l * 8)     = o0;
        *(float4*)(hout + (size_t)node * F1 + l * 8 + 4) = o1;
    }
}

// ---------------- layer 2 agg: warp/node, half-warp/edge, depth-2 prefetch ----------------
__global__ __launch_bounds__(256) void agg2_kernel(
    const float* __restrict__ xc, const int* __restrict__ rowptr,
    const int* __restrict__ csrsrc, const float* __restrict__ att,
    const float* __restrict__ bias, float* __restrict__ out)
{
    int node = (blockIdx.x * blockDim.x + threadIdx.x) >> 5;
    int lane = threadIdx.x & 31;
    if (node >= NN) return;
    int sub = lane >> 4, l = lane & 15;
    int base = l * 10;   // head = l>>2

    float2 vr[5], va[5];
    const float* vp = xc + (size_t)node * 320 + 160 + base;
    #pragma unroll
    for (int j = 0; j < 5; j++) {
        vr[j] = *(const float2*)(vp + 2 * j);
        va[j] = *(const float2*)(att + base + 2 * j);
    }

    int beg = rowptr[node], end = rowptr[node + 1];
    int iters = (end - beg + 1) >> 1;

    float2 acc[5];
    #pragma unroll
    for (int j = 0; j < 5; j++) acc[j] = make_float2(0.f, 0.f);
    float ssum = 0.f;

    int idx = beg + sub;
    bool v = idx < end;
    int s = v ? csrsrc[idx] : csrsrc[beg];
    float2 cur[5];
    {
        const float* sp = xc + (size_t)s * 320 + base;
        #pragma unroll
        for (int j = 0; j < 5; j++) cur[j] = *(const float2*)(sp + 2 * j);
    }

    for (int it = 0; it < iters; it++) {
        int idxn = idx + 2;
        bool vn = idxn < end;
        int sn = vn ? csrsrc[idxn] : csrsrc[beg];
        float2 nxt[5];
        {
            const float* sp = xc + (size_t)sn * 320 + base;
            #pragma unroll
            for (int j = 0; j < 5; j++) nxt[j] = *(const float2*)(sp + 2 * j);
        }
        float sum = 0.f;
        #pragma unroll
        for (int j = 0; j < 5; j++) {
            float g = cur[j].x + vr[j].x; g = g > 0.f ? g : SLOPE * g; sum += g * va[j].x;
            g       = cur[j].y + vr[j].y; g = g > 0.f ? g : SLOPE * g; sum += g * va[j].y;
        }
        sum += __shfl_xor_sync(FULLMASK, sum, 1);
        sum += __shfl_xor_sync(FULLMASK, sum, 2);
        float a = v ? __expf(sum) : 0.f;
        #pragma unroll
        for (int j = 0; j < 5; j++) { acc[j].x += a * cur[j].x; acc[j].y += a * cur[j].y; }
        ssum += a;
        #pragma unroll
        for (int j = 0; j < 5; j++) cur[j] = nxt[j];
        v = vn; idx = idxn;
    }

    #pragma unroll
    for (int j = 0; j < 5; j++) {
        acc[j].x += __shfl_xor_sync(FULLMASK, acc[j].x, 16);
        acc[j].y += __shfl_xor_sync(FULLMASK, acc[j].y, 16);
    }
    ssum += __shfl_xor_sync(FULLMASK, ssum, 16);

    float inv = 1.f / (ssum + 1e-16f);
    #pragma unroll
    for (int j = 0; j < 5; j++) {
        float vx = acc[j].x * inv, vy = acc[j].y * inv;
        vx += __shfl_xor_sync(FULLMASK, vx, 4);
        vx += __shfl_xor_sync(FULLMASK, vx, 8);
        vy += __shfl_xor_sync(FULLMASK, vy, 4);
        vy += __shfl_xor_sync(FULLMASK, vy, 8);
        acc[j].x = vx; acc[j].y = vy;
    }

    if (sub == 0 && l < 4) {
        #pragma unroll
        for (int j = 0; j < 5; j++) {
            float2 o;
            o.x = 0.25f * acc[j].x + bias[base + 2 * j];
            o.y = 0.25f * acc[j].y + bias[base + 2 * j + 1];
            *(float2*)(out + (size_t)node * OUT_DIM + base + 2 * j) = o;
        }
    }
}

// ---------------- host ----------------
struct Ptrs {
    float *xc1, *xc2, *h;
    int *deg, *rowptr, *csrsrc;
};
static Ptrs P;
static cudaStream_t g_s2;
static cudaEvent_t g_ev1, g_ev2, g_evA[NCHUNK], g_evG;
static bool g_init = false;

extern "C" void kernel_launch(void* const* d_in, const int* in_sizes, int n_in,
                              void* d_out, int out_size)
{
    if (!g_init) {
        cudaGetSymbolAddress((void**)&P.xc1,    g_xc1);
        cudaGetSymbolAddress((void**)&P.xc2,    g_xc2);
        cudaGetSymbolAddress((void**)&P.h,      g_h);
        cudaGetSymbolAddress((void**)&P.deg,    g_deg);
        cudaGetSymbolAddress((void**)&P.rowptr, g_rowptr);
        cudaGetSymbolAddress((void**)&P.csrsrc, g_csrsrc);
        cudaStreamCreateWithFlags(&g_s2, cudaStreamNonBlocking);
        cudaEventCreateWithFlags(&g_ev1, cudaEventDisableTiming);
        cudaEventCreateWithFlags(&g_ev2, cudaEventDisableTiming);
        for (int c = 0; c < NCHUNK; c++)
            cudaEventCreateWithFlags(&g_evA[c], cudaEventDisableTiming);
        cudaEventCreateWithFlags(&g_evG, cudaEventDisableTiming);
        g_init = true;
    }

    const float* x     = (const float*)d_in[0];
    const int*   ei    = (const int*)  d_in[1];
    const float* Wl1   = (const float*)d_in[2];
    const float* bl1   = (const float*)d_in[3];
    const float* Wr1   = (const float*)d_in[4];
    const float* br1   = (const float*)d_in[5];
    const float* att1  = (const float*)d_in[6];
    const float* bias1 = (const float*)d_in[7];
    const float* Wl2   = (const float*)d_in[8];
    const float* bl2   = (const float*)d_in[9];
    const float* Wr2   = (const float*)d_in[10];
    const float* br2   = (const float*)d_in[11];
    const float* att2  = (const float*)d_in[12];
    const float* bias2 = (const float*)d_in[13];
    float* out = (float*)d_out;

    const int* esrc = ei;
    const int* edst = ei + EE;

    // fork: CSR build on side stream, concurrent with GEMM1
    cudaEventRecord(g_ev1, 0);
    cudaStreamWaitEvent(g_s2, g_ev1, 0);
    cudaMemsetAsync(P.deg, 0, NN * sizeof(int), g_s2);
    count_kernel<<<(ET + 255) / 256, 256, 0, g_s2>>>(edst);
    scan_kernel<<<1, 1024, 0, g_s2>>>();
    scatter_kernel<<<(ET + 255) / 256, 256, 0, g_s2>>>(esrc, edst);
    cudaEventRecord(g_ev2, g_s2);

    // ----- layer 1 GEMM (main stream, full) -----
    {
        dim3 grid(2, (NN + 127) / 128);
        gemm_tf32_fused<<<grid, 256>>>(x, Wl1, Wr1, bl1, br1, P.xc1, NN, IN_DIM, F1, 0);
    }
    cudaStreamWaitEvent(0, g_ev2, 0);

    // ----- agg1 chunks (main) pipelined with gemm2 chunks (side) -----
    for (int c = 0; c < NCHUNK; c++) {
        int lo = c * CHSZ;
        int hi = (c == NCHUNK - 1) ? NN : lo + CHSZ;
        int nwarp = hi - lo;
        agg1_kernel<<<(nwarp * 32 + 255) / 256, 256>>>(
            P.xc1, P.rowptr, P.csrsrc, att1, bias1, P.h, lo, hi);
        cudaEventRecord(g_evA[c], 0);

        cudaStreamWaitEvent(g_s2, g_evA[c], 0);
        dim3 grid(3, (hi - lo + 127) / 128);
        gemm_tf32_fused<<<grid, 256, 0, g_s2>>>(
            P.h, Wl2, Wr2, bl2, br2, P.xc2, NN, F1, F2, lo);
    }
    cudaEventRecord(g_evG, g_s2);
    cudaStreamWaitEvent(0, g_evG, 0);

    // ----- layer 2 agg (full) -----
    agg2_kernel<<<(NN * 32 + 255) / 256, 256>>>(P.xc2, P.rowptr, P.csrsrc, att2, bias2, out);
}

// round 11
// speedup vs baseline: 1.2530x; 1.2388x over previous
#include <cuda_runtime.h>
#include <cstdint>

#define NN      50000
#define EE      800000
#define ET      (EE + NN)
#define IN_DIM  256
#define HID     32
#define HEADS   4
#define OUT_DIM 40
#define F1      128
#define F2      160
#define SLOPE   0.2f
#define FULLMASK 0xffffffffu

// ---------------- scratch ----------------
__device__ float    g_xc1[(size_t)NN * 256];   // [xl1 | xr1]
__device__ float    g_xc2[(size_t)NN * 320];   // [xl2 | xr2]
__device__ float    g_h  [(size_t)NN * F1];
__device__ uint32_t g_Wc1[IN_DIM * 2 * F1];    // tf32, concatenated [Wl1 | Wr1]
__device__ uint32_t g_Wc2[F1 * 2 * F2];        // tf32, concatenated [Wl2 | Wr2]
__device__ int      g_deg[NN];
__device__ int      g_rowptr[NN + 1];
__device__ int      g_cursor[NN];
__device__ int      g_csrsrc[ET];

// ---------------- helpers ----------------
__device__ __forceinline__ uint32_t f2tf(float f) {
    uint32_t r;
    asm("cvt.rna.tf32.f32 %0, %1;" : "=r"(r) : "f"(f));
    return r;
}
__device__ __forceinline__ void cpa16(uint32_t d, const void* s) {
    asm volatile("cp.async.cg.shared.global [%0], [%1], 16;"
                 :: "r"(d), "l"(s));
}

// ---------------- weight prep: concat + tf32 convert ----------------
__global__ void prep_w_kernel(const float* __restrict__ Wl, const float* __restrict__ Wr,
                              uint32_t* __restrict__ Wc, int K, int Nh)
{
    int total = K * 2 * Nh;
    for (int idx = blockIdx.x * blockDim.x + threadIdx.x; idx < total;
         idx += gridDim.x * blockDim.x) {
        int k = idx / (2 * Nh);
        int c = idx % (2 * Nh);
        float v = (c < Nh) ? Wl[k * Nh + c] : Wr[k * Nh + (c - Nh)];
        Wc[idx] = f2tf(v);
    }
}

// ---------------- CSR build ----------------
__global__ void count_kernel(const int* __restrict__ edst)
{
    int idx = blockIdx.x * blockDim.x + threadIdx.x;
    if (idx >= ET) return;
    int d = (idx < EE) ? edst[idx] : idx - EE;
    atomicAdd(&g_deg[d], 1);
}

__global__ void scan_kernel()
{
    __shared__ int ssum[1024];
    int t = threadIdx.x;
    const int CH = (NN + 1023) / 1024;
    int lo = t * CH;
    int hi = min(lo + CH, NN);
    int s = 0;
    for (int i = lo; i < hi; i++) s += g_deg[i];
    ssum[t] = s;
    __syncthreads();
    for (int off = 1; off < 1024; off <<= 1) {
        int v = (t >= off) ? ssum[t - off] : 0;
        __syncthreads();
        ssum[t] += v;
        __syncthreads();
    }
    int base = (t == 0) ? 0 : ssum[t - 1];
    for (int i = lo; i < hi; i++) {
        g_rowptr[i] = base;
        g_cursor[i] = base;
        base += g_deg[i];
    }
    if (t == 0) g_rowptr[NN] = ET;
}

__global__ void scatter_kernel(const int* __restrict__ esrc, const int* __restrict__ edst)
{
    int idx = blockIdx.x * blockDim.x + threadIdx.x;
    if (idx >= ET) return;
    int s, d;
    if (idx < EE) { s = esrc[idx]; d = edst[idx]; }
    else          { s = d = idx - EE; }
    int pos = atomicAdd(&g_cursor[d], 1);
    g_csrsrc[pos] = s;
}

// ---------------- TF32 GEMM: pre-converted weights, cp.async double-buffered ----------------
// C[M, N] = A[M,K] @ Wc(tf32) + [bl | br],  N = 2*Nh
__global__ __launch_bounds__(256, 2) void gemm_tf32_fused(
    const float* __restrict__ A, const uint32_t* __restrict__ Wc,
    const float* __restrict__ bl, const float* __restrict__ br,
    float* __restrict__ C, int M, int K, int Nh)
{
    const int N = 2 * Nh;
    __shared__ uint32_t As[2][16][136];
    __shared__ uint32_t Bs[2][16][136];
    int tid = threadIdx.x, lane = tid & 31, warp = tid >> 5;
    int wm = warp & 3, wn = warp >> 2;
    int rowBase = blockIdx.y * 128, colBase = blockIdx.x * 128;
    int grp = lane >> 2, tig = lane & 3;

    float acc[2][8][4];
    #pragma unroll
    for (int mt = 0; mt < 2; mt++)
        #pragma unroll
        for (int nt = 0; nt < 8; nt++)
            #pragma unroll
            for (int c = 0; c < 4; c++) acc[mt][nt][c] = 0.f;

    int nIter = K >> 4;
    int brow = tid >> 4;          // 0..15
    int bcol = (tid & 15) * 8;    // 0..120
    bool bok0 = (colBase + bcol)     < N;
    bool bok1 = (colBase + bcol + 4) < N;

    float4 pa, pb;
    {
        int gr = rowBase + (tid >> 1);
        int kc = (tid & 1) * 8;
        pa = make_float4(0.f, 0.f, 0.f, 0.f); pb = pa;
        if (gr < M) {
            pa = *(const float4*)(A + (size_t)gr * K + kc);
            pb = *(const float4*)(A + (size_t)gr * K + kc + 4);
        }
    }
    {
        const uint32_t* src = Wc + (size_t)brow * N + colBase + bcol;
        uint32_t d = (uint32_t)__cvta_generic_to_shared(&Bs[0][brow][bcol]);
        if (bok0) cpa16(d, src);
        if (bok1) cpa16(d + 16, src + 4);
    }
    {
        int r = tid >> 1, c4 = (tid & 1) * 8;
        As[0][c4 + 0][r] = f2tf(pa.x); As[0][c4 + 1][r] = f2tf(pa.y);
        As[0][c4 + 2][r] = f2tf(pa.z); As[0][c4 + 3][r] = f2tf(pa.w);
        As[0][c4 + 4][r] = f2tf(pb.x); As[0][c4 + 5][r] = f2tf(pb.y);
        As[0][c4 + 6][r] = f2tf(pb.z); As[0][c4 + 7][r] = f2tf(pb.w);
    }
    asm volatile("cp.async.commit_group;");

    int buf = 0;
    for (int it = 0; it < nIter; it++) {
        asm volatile("cp.async.wait_group 0;");
        __syncthreads();
        bool more = (it + 1 < nIter);
        if (more) {
            int k0 = (it + 1) << 4;
            int gr = rowBase + (tid >> 1);
            int kc = k0 + (tid & 1) * 8;
            pa = make_float4(0.f, 0.f, 0.f, 0.f); pb = pa;
            if (gr < M) {
                pa = *(const float4*)(A + (size_t)gr * K + kc);
                pb = *(const float4*)(A + (size_t)gr * K + kc + 4);
            }
            const uint32_t* src = Wc + (size_t)(k0 + brow) * N + colBase + bcol;
            uint32_t d = (uint32_t)__cvta_generic_to_shared(&Bs[buf ^ 1][brow][bcol]);
            if (bok0) cpa16(d, src);
            if (bok1) cpa16(d + 16, src + 4);
            asm volatile("cp.async.commit_group;");
        }

        #pragma unroll
        for (int ks = 0; ks < 16; ks += 8) {
            uint32_t af[2][4], bf[8][2];
            #pragma unroll
            for (int mt = 0; mt < 2; mt++) {
                int m = wm * 32 + mt * 16;
                af[mt][0] = As[buf][ks + tig][m + grp];
                af[mt][1] = As[buf][ks + tig][m + grp + 8];
                af[mt][2] = As[buf][ks + tig + 4][m + grp];
                af[mt][3] = As[buf][ks + tig + 4][m + grp + 8];
            }
            #pragma unroll
            for (int nt = 0; nt < 8; nt++) {
                int nb = wn * 64 + nt * 8;
                bf[nt][0] = Bs[buf][ks + tig][nb + grp];
                bf[nt][1] = Bs[buf][ks + tig + 4][nb + grp];
            }
            #pragma unroll
            for (int mt = 0; mt < 2; mt++)
                #pragma unroll
                for (int nt = 0; nt < 8; nt++) {
                    asm volatile(
                        "mma.sync.aligned.m16n8k8.row.col.f32.tf32.tf32.f32 "
                        "{%0,%1,%2,%3}, {%4,%5,%6,%7}, {%8,%9}, {%0,%1,%2,%3};"
                        : "+f"(acc[mt][nt][0]), "+f"(acc[mt][nt][1]),
                          "+f"(acc[mt][nt][2]), "+f"(acc[mt][nt][3])
                        : "r"(af[mt][0]), "r"(af[mt][1]), "r"(af[mt][2]), "r"(af[mt][3]),
                          "r"(bf[nt][0]), "r"(bf[nt][1]));
                }
        }

        if (more) {
            int r = tid >> 1, c4 = (tid & 1) * 8;
            int b = buf ^ 1;
            As[b][c4 + 0][r] = f2tf(pa.x); As[b][c4 + 1][r] = f2tf(pa.y);
            As[b][c4 + 2][r] = f2tf(pa.z); As[b][c4 + 3][r] = f2tf(pa.w);
            As[b][c4 + 4][r] = f2tf(pb.x); As[b][c4 + 5][r] = f2tf(pb.y);
            As[b][c4 + 6][r] = f2tf(pb.z); As[b][c4 + 7][r] = f2tf(pb.w);
        }
        buf ^= 1;
    }

    #pragma unroll
    for (int mt = 0; mt < 2; mt++) {
        #pragma unroll
        for (int nt = 0; nt < 8; nt++) {
            int row0 = rowBase + wm * 32 + mt * 16 + grp;
            int col0 = colBase + wn * 64 + nt * 8 + tig * 2;
            if (col0 < N) {
                float b0 = (col0     < Nh) ? bl[col0]     : br[col0 - Nh];
                float b1 = (col0 + 1 < Nh) ? bl[col0 + 1] : br[col0 + 1 - Nh];
                if (row0 < M) {
                    float2 o = make_float2(acc[mt][nt][0] + b0, acc[mt][nt][1] + b1);
                    *(float2*)(C + (size_t)row0 * N + col0) = o;
                }
                if (row0 + 8 < M) {
                    float2 o = make_float2(acc[mt][nt][2] + b0, acc[mt][nt][3] + b1);
                    *(float2*)(C + (size_t)(row0 + 8) * N + col0) = o;
                }
            }
        }
    }
}

// ---------------- layer 1 agg: warp/node, half-warp/edge, depth-2 prefetch ----------------
__global__ __launch_bounds__(256) void agg1_kernel(
    const float* __restrict__ xc, const int* __restrict__ rowptr,
    const int* __restrict__ csrsrc, const float* __restrict__ att,
    const float* __restrict__ bias, float* __restrict__ hout)
{
    int node = (blockIdx.x * blockDim.x + threadIdx.x) >> 5;
    int lane = threadIdx.x & 31;
    if (node >= NN) return;
    int sub = lane >> 4, l = lane & 15;

    const float* vp = xc + (size_t)node * 256 + 128 + l * 8;
    float4 vr0 = *(const float4*)(vp);
    float4 vr1 = *(const float4*)(vp + 4);
    float4 va0 = *(const float4*)(att + l * 8);
    float4 va1 = *(const float4*)(att + l * 8 + 4);

    int beg = rowptr[node], end = rowptr[node + 1];
    int iters = (end - beg + 1) >> 1;

    float4 acc0 = make_float4(0.f, 0.f, 0.f, 0.f);
    float4 acc1 = make_float4(0.f, 0.f, 0.f, 0.f);
    float ssum = 0.f;

    int idx = beg + sub;
    bool v = idx < end;
    int s = v ? csrsrc[idx] : csrsrc[beg];
    const float* sp = xc + (size_t)s * 256 + l * 8;
    float4 c0 = *(const float4*)sp;
    float4 c1 = *(const float4*)(sp + 4);

    for (int it = 0; it < iters; it++) {
        int idxn = idx + 2;
        bool vn = idxn < end;
        int sn = vn ? csrsrc[idxn] : csrsrc[beg];
        const float* np = xc + (size_t)sn * 256 + l * 8;
        float4 n0 = *(const float4*)np;
        float4 n1 = *(const float4*)(np + 4);

        float g, sum = 0.f;
        g = c0.x + vr0.x; g = g > 0.f ? g : SLOPE * g; sum += g * va0.x;
        g = c0.y + vr0.y; g = g > 0.f ? g : SLOPE * g; sum += g * va0.y;
        g = c0.z + vr0.z; g = g > 0.f ? g : SLOPE * g; sum += g * va0.z;
        g = c0.w + vr0.w; g = g > 0.f ? g : SLOPE * g; sum += g * va0.w;
        g = c1.x + vr1.x; g = g > 0.f ? g : SLOPE * g; sum += g * va1.x;
        g = c1.y + vr1.y; g = g > 0.f ? g : SLOPE * g; sum += g * va1.y;
        g = c1.z + vr1.z; g = g > 0.f ? g : SLOPE * g; sum += g * va1.z;
        g = c1.w + vr1.w; g = g > 0.f ? g : SLOPE * g; sum += g * va1.w;
        sum += __shfl_xor_sync(FULLMASK, sum, 1);
        sum += __shfl_xor_sync(FULLMASK, sum, 2);
        float a = v ? __expf(sum) : 0.f;
        acc0.x += a * c0.x; acc0.y += a * c0.y; acc0.z += a * c0.z; acc0.w += a * c0.w;
        acc1.x += a * c1.x; acc1.y += a * c1.y; acc1.z += a * c1.z; acc1.w += a * c1.w;
        ssum += a;
        c0 = n0; c1 = n1; v = vn; idx = idxn;
    }

    acc0.x += __shfl_xor_sync(FULLMASK, acc0.x, 16);
    acc0.y += __shfl_xor_sync(FULLMASK, acc0.y, 16);
    acc0.z += __shfl_xor_sync(FULLMASK, acc0.z, 16);
    acc0.w += __shfl_xor_sync(FULLMASK, acc0.w, 16);
    acc1.x += __shfl_xor_sync(FULLMASK, acc1.x, 16);
    acc1.y += __shfl_xor_sync(FULLMASK, acc1.y, 16);
    acc1.z += __shfl_xor_sync(FULLMASK, acc1.z, 16);
    acc1.w += __shfl_xor_sync(FULLMASK, acc1.w, 16);
    ssum   += __shfl_xor_sync(FULLMASK, ssum,   16);

    if (sub == 0) {
        float inv = 1.f / (ssum + 1e-16f);
        float4 b0 = *(const float4*)(bias + l * 8);
        float4 b1 = *(const float4*)(bias + l * 8 + 4);
        float4 o0, o1;
        o0.x = acc0.x * inv + b0.x; o0.y = acc0.y * inv + b0.y;
        o0.z = acc0.z * inv + b0.z; o0.w = acc0.w * inv + b0.w;
        o1.x = acc1.x * inv + b1.x; o1.y = acc1.y * inv + b1.y;
        o1.z = acc1.z * inv + b1.z; o1.w = acc1.w * inv + b1.w;
        o0.x = o0.x > 0.f ? o0.x : (__expf(o0.x) - 1.f);
        o0.y = o0.y > 0.f ? o0.y : (__expf(o0.y) - 1.f);
        o0.z = o0.z > 0.f ? o0.z : (__expf(o0.z) - 1.f);
        o0.w = o0.w > 0.f ? o0.w : (__expf(o0.w) - 1.f);
        o1.x = o1.x > 0.f ? o1.x : (__expf(o1.x) - 1.f);
        o1.y = o1.y > 0.f ? o1.y : (__expf(o1.y) - 1.f);
        o1.z = o1.z > 0.f ? o1.z : (__expf(o1.z) - 1.f);
        o1.w = o1.w > 0.f ? o1.w : (__expf(o1.w) - 1.f);
        *(float4*)(hout + (size_t)node * F1 + l * 8)     = o0;
        *(float4*)(hout + (size_t)node * F1 + l * 8 + 4) = o1;
    }
}

// ---------------- layer 2 agg: warp/node, half-warp/edge, depth-2 prefetch ----------------
__global__ __launch_bounds__(256) void agg2_kernel(
    const float* __restrict__ xc, const int* __restrict__ rowptr,
    const int* __restrict__ csrsrc, const float* __restrict__ att,
    const float* __restrict__ bias, float* __restrict__ out)
{
    int node = (blockIdx.x * blockDim.x + threadIdx.x) >> 5;
    int lane = threadIdx.x & 31;
    if (node >= NN) return;
    int sub = lane >> 4, l = lane & 15;
    int base = l * 10;   // head = l>>2

    float2 vr[5], va[5];
    const float* vp = xc + (size_t)node * 320 + 160 + base;
    #pragma unroll
    for (int j = 0; j < 5; j++) {
        vr[j] = *(const float2*)(vp + 2 * j);
        va[j] = *(const float2*)(att + base + 2 * j);
    }

    int beg = rowptr[node], end = rowptr[node + 1];
    int iters = (end - beg + 1) >> 1;

    float2 acc[5];
    #pragma unroll
    for (int j = 0; j < 5; j++) acc[j] = make_float2(0.f, 0.f);
    float ssum = 0.f;

    int idx = beg + sub;
    bool v = idx < end;
    int s = v ? csrsrc[idx] : csrsrc[beg];
    float2 cur[5];
    {
        const float* sp = xc + (size_t)s * 320 + base;
        #pragma unroll
        for (int j = 0; j < 5; j++) cur[j] = *(const float2*)(sp + 2 * j);
    }

    for (int it = 0; it < iters; it++) {
        int idxn = idx + 2;
        bool vn = idxn < end;
        int sn = vn ? csrsrc[idxn] : csrsrc[beg];
        float2 nxt[5];
        {
            const float* sp = xc + (size_t)sn * 320 + base;
            #pragma unroll
            for (int j = 0; j < 5; j++) nxt[j] = *(const float2*)(sp + 2 * j);
        }
        float sum = 0.f;
        #pragma unroll
        for (int j = 0; j < 5; j++) {
            float g = cur[j].x + vr[j].x; g = g > 0.f ? g : SLOPE * g; sum += g * va[j].x;
            g       = cur[j].y + vr[j].y; g = g > 0.f ? g : SLOPE * g; sum += g * va[j].y;
        }
        sum += __shfl_xor_sync(FULLMASK, sum, 1);
        sum += __shfl_xor_sync(FULLMASK, sum, 2);
        float a = v ? __expf(sum) : 0.f;
        #pragma unroll
        for (int j = 0; j < 5; j++) { acc[j].x += a * cur[j].x; acc[j].y += a * cur[j].y; }
        ssum += a;
        #pragma unroll
        for (int j = 0; j < 5; j++) cur[j] = nxt[j];
        v = vn; idx = idxn;
    }

    #pragma unroll
    for (int j = 0; j < 5; j++) {
        acc[j].x += __shfl_xor_sync(FULLMASK, acc[j].x, 16);
        acc[j].y += __shfl_xor_sync(FULLMASK, acc[j].y, 16);
    }
    ssum += __shfl_xor_sync(FULLMASK, ssum, 16);

    float inv = 1.f / (ssum + 1e-16f);
    #pragma unroll
    for (int j = 0; j < 5; j++) {
        float vx = acc[j].x * inv, vy = acc[j].y * inv;
        vx += __shfl_xor_sync(FULLMASK, vx, 4);
        vx += __shfl_xor_sync(FULLMASK, vx, 8);
        vy += __shfl_xor_sync(FULLMASK, vy, 4);
        vy += __shfl_xor_sync(FULLMASK, vy, 8);
        acc[j].x = vx; acc[j].y = vy;
    }

    if (sub == 0 && l < 4) {
        #pragma unroll
        for (int j = 0; j < 5; j++) {
            float2 o;
            o.x = 0.25f * acc[j].x + bias[base + 2 * j];
            o.y = 0.25f * acc[j].y + bias[base + 2 * j + 1];
            *(float2*)(out + (size_t)node * OUT_DIM + base + 2 * j) = o;
        }
    }
}

// ---------------- host ----------------
struct Ptrs {
    float *xc1, *xc2, *h;
    uint32_t *Wc1, *Wc2;
    int *deg, *rowptr, *csrsrc;
};
static Ptrs P;
static cudaStream_t g_s2;
static cudaEvent_t g_ev1, g_ev2;
static bool g_init = false;

extern "C" void kernel_launch(void* const* d_in, const int* in_sizes, int n_in,
                              void* d_out, int out_size)
{
    if (!g_init) {
        cudaGetSymbolAddress((void**)&P.xc1,    g_xc1);
        cudaGetSymbolAddress((void**)&P.xc2,    g_xc2);
        cudaGetSymbolAddress((void**)&P.h,      g_h);
        cudaGetSymbolAddress((void**)&P.Wc1,    g_Wc1);
        cudaGetSymbolAddress((void**)&P.Wc2,    g_Wc2);
        cudaGetSymbolAddress((void**)&P.deg,    g_deg);
        cudaGetSymbolAddress((void**)&P.rowptr, g_rowptr);
        cudaGetSymbolAddress((void**)&P.csrsrc, g_csrsrc);
        cudaStreamCreateWithFlags(&g_s2, cudaStreamNonBlocking);
        cudaEventCreateWithFlags(&g_ev1, cudaEventDisableTiming);
        cudaEventCreateWithFlags(&g_ev2, cudaEventDisableTiming);
        g_init = true;
    }

    const float* x     = (const float*)d_in[0];
    const int*   ei    = (const int*)  d_in[1];
    const float* Wl1   = (const float*)d_in[2];
    const float* bl1   = (const float*)d_in[3];
    const float* Wr1   = (const float*)d_in[4];
    const float* br1   = (const float*)d_in[5];
    const float* att1  = (const float*)d_in[6];
    const float* bias1 = (const float*)d_in[7];
    const float* Wl2   = (const float*)d_in[8];
    const float* bl2   = (const float*)d_in[9];
    const float* Wr2   = (const float*)d_in[10];
    const float* br2   = (const float*)d_in[11];
    const float* att2  = (const float*)d_in[12];
    const float* bias2 = (const float*)d_in[13];
    float* out = (float*)d_out;

    const int* esrc = ei;
    const int* edst = ei + EE;

    // fork: CSR build + prep2 on side stream, concurrent with prep1+GEMM1
    cudaEventRecord(g_ev1, 0);
    cudaStreamWaitEvent(g_s2, g_ev1, 0);
    cudaMemsetAsync(P.deg, 0, NN * sizeof(int), g_s2);
    count_kernel<<<(ET + 255) / 256, 256, 0, g_s2>>>(edst);
    scan_kernel<<<1, 1024, 0, g_s2>>>();
    scatter_kernel<<<(ET + 255) / 256, 256, 0, g_s2>>>(esrc, edst);
    prep_w_kernel<<<128, 256, 0, g_s2>>>(Wl2, Wr2, P.Wc2, F1, F2);
    cudaEventRecord(g_ev2, g_s2);

    // ----- layer 1: prep + GEMM (main stream) -----
    prep_w_kernel<<<128, 256>>>(Wl1, Wr1, P.Wc1, IN_DIM, F1);
    {
        dim3 grid(2, (NN + 127) / 128);
        gemm_tf32_fused<<<grid, 256>>>(x, P.Wc1, bl1, br1, P.xc1, NN, IN_DIM, F1);
    }
    cudaStreamWaitEvent(0, g_ev2, 0);
    agg1_kernel<<<(NN * 32 + 255) / 256, 256>>>(P.xc1, P.rowptr, P.csrsrc, att1, bias1, P.h);

    // ----- layer 2 -----
    {
        dim3 grid(3, (NN + 127) / 128);
        gemm_tf32_fused<<<grid, 256>>>(P.h, P.Wc2, bl2, br2, P.xc2, NN, F1, F2);
    }
    agg2_kernel<<<(NN * 32 + 255) / 256, 256>>>(P.xc2, P.rowptr, P.csrsrc, att2, bias2, out);
}

// round 12
// speedup vs baseline: 1.2716x; 1.0149x over previous
#include <cuda_runtime.h>
#include <cstdint>

#define NN      50000
#define EE      800000
#define ET      (EE + NN)
#define IN_DIM  256
#define HID     32
#define HEADS   4
#define OUT_DIM 40
#define F1      128
#define F2      160
#define SLOPE   0.2f
#define FULLMASK 0xffffffffu

// ---------------- scratch ----------------
__device__ float    g_xc1[(size_t)NN * 256];   // [xl1 | xr1]
__device__ float    g_xc2[(size_t)NN * 320];   // [xl2 | xr2]
__device__ float    g_h  [(size_t)NN * F1];
__device__ uint32_t g_Wc1[IN_DIM * 2 * F1];    // tf32, concatenated [Wl1 | Wr1]
__device__ uint32_t g_Wc2[F1 * 2 * F2];        // tf32, concatenated [Wl2 | Wr2]
__device__ int      g_deg[NN];
__device__ int      g_rowptr[NN + 1];
__device__ int      g_cursor[NN];
__device__ int      g_csrsrc[ET];

// ---------------- helpers ----------------
__device__ __forceinline__ uint32_t f2tf(float f) {
    uint32_t r;
    asm("cvt.rna.tf32.f32 %0, %1;" : "=r"(r) : "f"(f));
    return r;
}
__device__ __forceinline__ void cpa16(uint32_t d, const void* s) {
    asm volatile("cp.async.cg.shared.global [%0], [%1], 16;"
                 :: "r"(d), "l"(s));
}

// ---------------- weight prep: concat + tf32 convert ----------------
__global__ void prep_w_kernel(const float* __restrict__ Wl, const float* __restrict__ Wr,
                              uint32_t* __restrict__ Wc, int K, int Nh)
{
    int total = K * 2 * Nh;
    for (int idx = blockIdx.x * blockDim.x + threadIdx.x; idx < total;
         idx += gridDim.x * blockDim.x) {
        int k = idx / (2 * Nh);
        int c = idx % (2 * Nh);
        float v = (c < Nh) ? Wl[k * Nh + c] : Wr[k * Nh + (c - Nh)];
        Wc[idx] = f2tf(v);
    }
}

// ---------------- CSR build ----------------
__global__ void count_kernel(const int* __restrict__ edst)
{
    int idx = blockIdx.x * blockDim.x + threadIdx.x;
    if (idx >= ET) return;
    int d = (idx < EE) ? edst[idx] : idx - EE;
    atomicAdd(&g_deg[d], 1);
}

__global__ void scan_kernel()
{
    __shared__ int ssum[1024];
    int t = threadIdx.x;
    const int CH = (NN + 1023) / 1024;
    int lo = t * CH;
    int hi = min(lo + CH, NN);
    int s = 0;
    for (int i = lo; i < hi; i++) s += g_deg[i];
    ssum[t] = s;
    __syncthreads();
    for (int off = 1; off < 1024; off <<= 1) {
        int v = (t >= off) ? ssum[t - off] : 0;
        __syncthreads();
        ssum[t] += v;
        __syncthreads();
    }
    int base = (t == 0) ? 0 : ssum[t - 1];
    for (int i = lo; i < hi; i++) {
        g_rowptr[i] = base;
        g_cursor[i] = base;
        base += g_deg[i];
    }
    if (t == 0) g_rowptr[NN] = ET;
}

__global__ void scatter_kernel(const int* __restrict__ esrc, const int* __restrict__ edst)
{
    int idx = blockIdx.x * blockDim.x + threadIdx.x;
    if (idx >= ET) return;
    int s, d;
    if (idx < EE) { s = esrc[idx]; d = edst[idx]; }
    else          { s = d = idx - EE; }
    int pos = atomicAdd(&g_cursor[d], 1);
    g_csrsrc[pos] = s;
}

// ---------------- TF32 GEMM: full cp.async staging (A raw fp32, B pre-tf32) ----------------
// C[M, N] = A[M,K] @ Wc(tf32) + [bl | br],  N = 2*Nh
// As_raw layout [m][k], k padded to 20: fragment bank = (20*grp + tig) % 32, conflict-free.
__global__ __launch_bounds__(256, 2) void gemm_tf32_fused(
    const float* __restrict__ A, const uint32_t* __restrict__ Wc,
    const float* __restrict__ bl, const float* __restrict__ br,
    float* __restrict__ C, int M, int K, int Nh)
{
    const int N = 2 * Nh;
    __shared__ float    As[2][128][20];
    __shared__ uint32_t Bs[2][16][136];
    int tid = threadIdx.x, lane = tid & 31, warp = tid >> 5;
    int wm = warp & 3, wn = warp >> 2;
    int rowBase = blockIdx.y * 128, colBase = blockIdx.x * 128;
    int grp = lane >> 2, tig = lane & 3;

    float acc[2][8][4];
    #pragma unroll
    for (int mt = 0; mt < 2; mt++)
        #pragma unroll
        for (int nt = 0; nt < 8; nt++)
            #pragma unroll
            for (int c = 0; c < 4; c++) acc[mt][nt][c] = 0.f;

    int nIter = K >> 4;
    // A staging: 2 chunks of 16B per thread
    int arow = tid >> 1;              // 0..127
    int akc  = (tid & 1) * 8;         // 0 or 8
    bool aok = (rowBase + arow) < M;
    const float* asrc = A + (size_t)(rowBase + arow) * K + akc;
    // B staging
    int brow = tid >> 4;              // 0..15
    int bcol = (tid & 15) * 8;        // 0..120
    bool bok0 = (colBase + bcol)     < N;
    bool bok1 = (colBase + bcol + 4) < N;
    const uint32_t* bsrc = Wc + (size_t)brow * N + colBase + bcol;

    // prologue: tile 0
    {
        uint32_t da = (uint32_t)__cvta_generic_to_shared(&As[0][arow][akc]);
        if (aok) { cpa16(da, asrc); cpa16(da + 16, asrc + 4); }
        uint32_t db = (uint32_t)__cvta_generic_to_shared(&Bs[0][brow][bcol]);
        if (bok0) cpa16(db, bsrc);
        if (bok1) cpa16(db + 16, bsrc + 4);
    }
    asm volatile("cp.async.commit_group;");

    int buf = 0;
    for (int it = 0; it < nIter; it++) {
        asm volatile("cp.async.wait_group 0;");
        __syncthreads();
        bool more = (it + 1 < nIter);
        if (more) {
            int k0 = (it + 1) << 4;
            int b = buf ^ 1;
            uint32_t da = (uint32_t)__cvta_generic_to_shared(&As[b][arow][akc]);
            if (aok) { cpa16(da, asrc + k0); cpa16(da + 16, asrc + k0 + 4); }
            uint32_t db = (uint32_t)__cvta_generic_to_shared(&Bs[b][brow][bcol]);
            if (bok0) cpa16(db, bsrc + (size_t)k0 * N);
            if (bok1) cpa16(db + 16, bsrc + (size_t)k0 * N + 4);
            asm volatile("cp.async.commit_group;");
        }

        #pragma unroll
        for (int ks = 0; ks < 16; ks += 8) {
            uint32_t af[2][4], bf[8][2];
            #pragma unroll
            for (int mt = 0; mt < 2; mt++) {
                int m = wm * 32 + mt * 16;
                af[mt][0] = f2tf(As[buf][m + grp][ks + tig]);
                af[mt][1] = f2tf(As[buf][m + grp + 8][ks + tig]);
                af[mt][2] = f2tf(As[buf][m + grp][ks + tig + 4]);
                af[mt][3] = f2tf(As[buf][m + grp + 8][ks + tig + 4]);
            }
            #pragma unroll
            for (int nt = 0; nt < 8; nt++) {
                int nb = wn * 64 + nt * 8;
                bf[nt][0] = Bs[buf][ks + tig][nb + grp];
                bf[nt][1] = Bs[buf][ks + tig + 4][nb + grp];
            }
            #pragma unroll
            for (int mt = 0; mt < 2; mt++)
                #pragma unroll
                for (int nt = 0; nt < 8; nt++) {
                    asm volatile(
                        "mma.sync.aligned.m16n8k8.row.col.f32.tf32.tf32.f32 "
                        "{%0,%1,%2,%3}, {%4,%5,%6,%7}, {%8,%9}, {%0,%1,%2,%3};"
                        : "+f"(acc[mt][nt][0]), "+f"(acc[mt][nt][1]),
                          "+f"(acc[mt][nt][2]), "+f"(acc[mt][nt][3])
                        : "r"(af[mt][0]), "r"(af[mt][1]), "r"(af[mt][2]), "r"(af[mt][3]),
                          "r"(bf[nt][0]), "r"(bf[nt][1]));
                }
        }
        buf ^= 1;
    }

    #pragma unroll
    for (int mt = 0; mt < 2; mt++) {
        #pragma unroll
        for (int nt = 0; nt < 8; nt++) {
            int row0 = rowBase + wm * 32 + mt * 16 + grp;
            int col0 = colBase + wn * 64 + nt * 8 + tig * 2;
            if (col0 < N) {
                float b0 = (col0     < Nh) ? bl[col0]     : br[col0 - Nh];
                float b1 = (col0 + 1 < Nh) ? bl[col0 + 1] : br[col0 + 1 - Nh];
                if (row0 < M) {
                    float2 o = make_float2(acc[mt][nt][0] + b0, acc[mt][nt][1] + b1);
                    *(float2*)(C + (size_t)row0 * N + col0) = o;
                }
                if (row0 + 8 < M) {
                    float2 o = make_float2(acc[mt][nt][2] + b0, acc[mt][nt][3] + b1);
                    *(float2*)(C + (size_t)(row0 + 8) * N + col0) = o;
                }
            }
        }
    }
}

// ---------------- layer 1 agg: warp/node, half-warp/edge, depth-2 prefetch ----------------
__global__ __launch_bounds__(256) void agg1_kernel(
    const float* __restrict__ xc, const int* __restrict__ rowptr,
    const int* __restrict__ csrsrc, const float* __restrict__ att,
    const float* __restrict__ bias, float* __restrict__ hout)
{
    int node = (blockIdx.x * blockDim.x + threadIdx.x) >> 5;
    int lane = threadIdx.x & 31;
    if (node >= NN) return;
    int sub = lane >> 4, l = lane & 15;

    const float* vp = xc + (size_t)node * 256 + 128 + l * 8;
    float4 vr0 = *(const float4*)(vp);
    float4 vr1 = *(const float4*)(vp + 4);
    float4 va0 = *(const float4*)(att + l * 8);
    float4 va1 = *(const float4*)(att + l * 8 + 4);

    int beg = rowptr[node], end = rowptr[node + 1];
    int iters = (end - beg + 1) >> 1;

    float4 acc0 = make_float4(0.f, 0.f, 0.f, 0.f);
    float4 acc1 = make_float4(0.f, 0.f, 0.f, 0.f);
    float ssum = 0.f;

    int idx = beg + sub;
    bool v = idx < end;
    int s = v ? csrsrc[idx] : csrsrc[beg];
    const float* sp = xc + (size_t)s * 256 + l * 8;
    float4 c0 = *(const float4*)sp;
    float4 c1 = *(const float4*)(sp + 4);

    for (int it = 0; it < iters; it++) {
        int idxn = idx + 2;
        bool vn = idxn < end;
        int sn = vn ? csrsrc[idxn] : csrsrc[beg];
        const float* np = xc + (size_t)sn * 256 + l * 8;
        float4 n0 = *(const float4*)np;
        float4 n1 = *(const float4*)(np + 4);

        float g, sum = 0.f;
        g = c0.x + vr0.x; g = g > 0.f ? g : SLOPE * g; sum += g * va0.x;
        g = c0.y + vr0.y; g = g > 0.f ? g : SLOPE * g; sum += g * va0.y;
        g = c0.z + vr0.z; g = g > 0.f ? g : SLOPE * g; sum += g * va0.z;
        g = c0.w + vr0.w; g = g > 0.f ? g : SLOPE * g; sum += g * va0.w;
        g = c1.x + vr1.x; g = g > 0.f ? g : SLOPE * g; sum += g * va1.x;
        g = c1.y + vr1.y; g = g > 0.f ? g : SLOPE * g; sum += g * va1.y;
        g = c1.z + vr1.z; g = g > 0.f ? g : SLOPE * g; sum += g * va1.z;
        g = c1.w + vr1.w; g = g > 0.f ? g : SLOPE * g; sum += g * va1.w;
        sum += __shfl_xor_sync(FULLMASK, sum, 1);
        sum += __shfl_xor_sync(FULLMASK, sum, 2);
        float a = v ? __expf(sum) : 0.f;
        acc0.x += a * c0.x; acc0.y += a * c0.y; acc0.z += a * c0.z; acc0.w += a * c0.w;
        acc1.x += a * c1.x; acc1.y += a * c1.y; acc1.z += a * c1.z; acc1.w += a * c1.w;
        ssum += a;
        c0 = n0; c1 = n1; v = vn; idx = idxn;
    }

    acc0.x += __shfl_xor_sync(FULLMASK, acc0.x, 16);
    acc0.y += __shfl_xor_sync(FULLMASK, acc0.y, 16);
    acc0.z += __shfl_xor_sync(FULLMASK, acc0.z, 16);
    acc0.w += __shfl_xor_sync(FULLMASK, acc0.w, 16);
    acc1.x += __shfl_xor_sync(FULLMASK, acc1.x, 16);
    acc1.y += __shfl_xor_sync(FULLMASK, acc1.y, 16);
    acc1.z += __shfl_xor_sync(FULLMASK, acc1.z, 16);
    acc1.w += __shfl_xor_sync(FULLMASK, acc1.w, 16);
    ssum   += __shfl_xor_sync(FULLMASK, ssum,   16);

    if (sub == 0) {
        float inv = 1.f / (ssum + 1e-16f);
        float4 b0 = *(const float4*)(bias + l * 8);
        float4 b1 = *(const float4*)(bias + l * 8 + 4);
        float4 o0, o1;
        o0.x = acc0.x * inv + b0.x; o0.y = acc0.y * inv + b0.y;
        o0.z = acc0.z * inv + b0.z; o0.w = acc0.w * inv + b0.w;
        o1.x = acc1.x * inv + b1.x; o1.y = acc1.y * inv + b1.y;
        o1.z = acc1.z * inv + b1.z; o1.w = acc1.w * inv + b1.w;
        o0.x = o0.x > 0.f ? o0.x : (__expf(o0.x) - 1.f);
        o0.y = o0.y > 0.f ? o0.y : (__expf(o0.y) - 1.f);
        o0.z = o0.z > 0.f ? o0.z : (__expf(o0.z) - 1.f);
        o0.w = o0.w > 0.f ? o0.w : (__expf(o0.w) - 1.f);
        o1.x = o1.x > 0.f ? o1.x : (__expf(o1.x) - 1.f);
        o1.y = o1.y > 0.f ? o1.y : (__expf(o1.y) - 1.f);
        o1.z = o1.z > 0.f ? o1.z : (__expf(o1.z) - 1.f);
        o1.w = o1.w > 0.f ? o1.w : (__expf(o1.w) - 1.f);
        *(float4*)(hout + (size_t)node * F1 + l * 8)     = o0;
        *(float4*)(hout + (size_t)node * F1 + l * 8 + 4) = o1;
    }
}

// ---------------- layer 2 agg: warp/node, half-warp/edge, depth-2 prefetch ----------------
__global__ __launch_bounds__(256) void agg2_kernel(
    const float* __restrict__ xc, const int* __restrict__ rowptr,
    const int* __restrict__ csrsrc, const float* __restrict__ att,
    const float* __restrict__ bias, float* __restrict__ out)
{
    int node = (blockIdx.x * blockDim.x + threadIdx.x) >> 5;
    int lane = threadIdx.x & 31;
    if (node >= NN) return;
    int sub = lane >> 4, l = lane & 15;
    int base = l * 10;   // head = l>>2

    float2 vr[5], va[5];
    const float* vp = xc + (size_t)node * 320 + 160 + base;
    #pragma unroll
    for (int j = 0; j < 5; j++) {
        vr[j] = *(const float2*)(vp + 2 * j);
        va[j] = *(const float2*)(att + base + 2 * j);
    }

    int beg = rowptr[node], end = rowptr[node + 1];
    int iters = (end - beg + 1) >> 1;

    float2 acc[5];
    #pragma unroll
    for (int j = 0; j < 5; j++) acc[j] = make_float2(0.f, 0.f);
    float ssum = 0.f;

    int idx = beg + sub;
    bool v = idx < end;
    int s = v ? csrsrc[idx] : csrsrc[beg];
    float2 cur[5];
    {
        const float* sp = xc + (size_t)s * 320 + base;
        #pragma unroll
        for (int j = 0; j < 5; j++) cur[j] = *(const float2*)(sp + 2 * j);
    }

    for (int it = 0; it < iters; it++) {
        int idxn = idx + 2;
        bool vn = idxn < end;
        int sn = vn ? csrsrc[idxn] : csrsrc[beg];
        float2 nxt[5];
        {
            const float* sp = xc + (size_t)sn * 320 + base;
            #pragma unroll
            for (int j = 0; j < 5; j++) nxt[j] = *(const float2*)(sp + 2 * j);
        }
        float sum = 0.f;
        #pragma unroll
        for (int j = 0; j < 5; j++) {
            float g = cur[j].x + vr[j].x; g = g > 0.f ? g : SLOPE * g; sum += g * va[j].x;
            g       = cur[j].y + vr[j].y; g = g > 0.f ? g : SLOPE * g; sum += g * va[j].y;
        }
        sum += __shfl_xor_sync(FULLMASK, sum, 1);
        sum += __shfl_xor_sync(FULLMASK, sum, 2);
        float a = v ? __expf(sum) : 0.f;
        #pragma unroll
        for (int j = 0; j < 5; j++) { acc[j].x += a * cur[j].x; acc[j].y += a * cur[j].y; }
        ssum += a;
        #pragma unroll
        for (int j = 0; j < 5; j++) cur[j] = nxt[j];
        v = vn; idx = idxn;
    }

    #pragma unroll
    for (int j = 0; j < 5; j++) {
        acc[j].x += __shfl_xor_sync(FULLMASK, acc[j].x, 16);
        acc[j].y += __shfl_xor_sync(FULLMASK, acc[j].y, 16);
    }
    ssum += __shfl_xor_sync(FULLMASK, ssum, 16);

    float inv = 1.f / (ssum + 1e-16f);
    #pragma unroll
    for (int j = 0; j < 5; j++) {
        float vx = acc[j].x * inv, vy = acc[j].y * inv;
        vx += __shfl_xor_sync(FULLMASK, vx, 4);
        vx += __shfl_xor_sync(FULLMASK, vx, 8);
        vy += __shfl_xor_sync(FULLMASK, vy, 4);
        vy += __shfl_xor_sync(FULLMASK, vy, 8);
        acc[j].x = vx; acc[j].y = vy;
    }

    if (sub == 0 && l < 4) {
        #pragma unroll
        for (int j = 0; j < 5; j++) {
            float2 o;
            o.x = 0.25f * acc[j].x + bias[base + 2 * j];
            o.y = 0.25f * acc[j].y + bias[base + 2 * j + 1];
            *(float2*)(out + (size_t)node * OUT_DIM + base + 2 * j) = o;
        }
    }
}

// ---------------- host ----------------
struct Ptrs {
    float *xc1, *xc2, *h;
    uint32_t *Wc1, *Wc2;
    int *deg, *rowptr, *csrsrc;
};
static Ptrs P;
static cudaStream_t g_s2;
static cudaEvent_t g_ev1, g_ev2;
static bool g_init = false;

extern "C" void kernel_launch(void* const* d_in, const int* in_sizes, int n_in,
                              void* d_out, int out_size)
{
    if (!g_init) {
        cudaGetSymbolAddress((void**)&P.xc1,    g_xc1);
        cudaGetSymbolAddress((void**)&P.xc2,    g_xc2);
        cudaGetSymbolAddress((void**)&P.h,      g_h);
        cudaGetSymbolAddress((void**)&P.Wc1,    g_Wc1);
        cudaGetSymbolAddress((void**)&P.Wc2,    g_Wc2);
        cudaGetSymbolAddress((void**)&P.deg,    g_deg);
        cudaGetSymbolAddress((void**)&P.rowptr, g_rowptr);
        cudaGetSymbolAddress((void**)&P.csrsrc, g_csrsrc);
        cudaStreamCreateWithFlags(&g_s2, cudaStreamNonBlocking);
        cudaEventCreateWithFlags(&g_ev1, cudaEventDisableTiming);
        cudaEventCreateWithFlags(&g_ev2, cudaEventDisableTiming);
        g_init = true;
    }

    const float* x     = (const float*)d_in[0];
    const int*   ei    = (const int*)  d_in[1];
    const float* Wl1   = (const float*)d_in[2];
    const float* bl1   = (const float*)d_in[3];
    const float* Wr1   = (const float*)d_in[4];
    const float* br1   = (const float*)d_in[5];
    const float* att1  = (const float*)d_in[6];
    const float* bias1 = (const float*)d_in[7];
    const float* Wl2   = (const float*)d_in[8];
    const float* bl2   = (const float*)d_in[9];
    const float* Wr2   = (const float*)d_in[10];
    const float* br2   = (const float*)d_in[11];
    const float* att2  = (const float*)d_in[12];
    const float* bias2 = (const float*)d_in[13];
    float* out = (float*)d_out;

    const int* esrc = ei;
    const int* edst = ei + EE;

    // fork: CSR build + prep2 on side stream, concurrent with prep1+GEMM1
    cudaEventRecord(g_ev1, 0);
    cudaStreamWaitEvent(g_s2, g_ev1, 0);
    cudaMemsetAsync(P.deg, 0, NN * sizeof(int), g_s2);
    count_kernel<<<(ET + 255) / 256, 256, 0, g_s2>>>(edst);
    scan_kernel<<<1, 1024, 0, g_s2>>>();
    scatter_kernel<<<(ET + 255) / 256, 256, 0, g_s2>>>(esrc, edst);
    prep_w_kernel<<<128, 256, 0, g_s2>>>(Wl2, Wr2, P.Wc2, F1, F2);
    cudaEventRecord(g_ev2, g_s2);

    // ----- layer 1: prep + GEMM (main stream) -----
    prep_w_kernel<<<128, 256>>>(Wl1, Wr1, P.Wc1, IN_DIM, F1);
    {
        dim3 grid(2, (NN + 127) / 128);
        gemm_tf32_fused<<<grid, 256>>>(x, P.Wc1, bl1, br1, P.xc1, NN, IN_DIM, F1);
    }
    cudaStreamWaitEvent(0, g_ev2, 0);
    agg1_kernel<<<(NN * 32 + 255) / 256, 256>>>(P.xc1, P.rowptr, P.csrsrc, att1, bias1, P.h);

    // ----- layer 2 -----
    {
        dim3 grid(3, (NN + 127) / 128);
        gemm_tf32_fused<<<grid, 256>>>(P.h, P.Wc2, bl2, br2, P.xc2, NN, F1, F2);
    }
    agg2_kernel<<<(NN * 32 + 255) / 256, 256>>>(P.xc2, P.rowptr, P.csrsrc, att2, bias2, out);
}

// round 13
// speedup vs baseline: 1.3398x; 1.0536x over previous
#include <cuda_runtime.h>
#include <cuda_fp16.h>
#include <cstdint>

#define NN      50000
#define EE      800000
#define ET      (EE + NN)
#define IN_DIM  256
#define HID     32
#define HEADS   4
#define OUT_DIM 40
#define F1      128
#define F2      160
#define SLOPE   0.2f
#define FULLMASK 0xffffffffu

// ---------------- scratch ----------------
__device__ float    g_xc1[(size_t)NN * 256];   // [unused | xr1] (xl1 lives in g_xlh1)
__device__ float    g_xc2[(size_t)NN * 320];   // [unused | xr2] (xl2 lives in g_xlh2)
__device__ __half   g_xlh1[(size_t)NN * F1];   // fp16 xl1 for gathers
__device__ __half   g_xlh2[(size_t)NN * F2];   // fp16 xl2 for gathers
__device__ float    g_h  [(size_t)NN * F1];
__device__ uint32_t g_Wc1[IN_DIM * 2 * F1];    // tf32, concatenated [Wl1 | Wr1]
__device__ uint32_t g_Wc2[F1 * 2 * F2];        // tf32, concatenated [Wl2 | Wr2]
__device__ int      g_deg[NN];
__device__ int      g_rowptr[NN + 1];
__device__ int      g_cursor[NN];
__device__ int      g_csrsrc[ET];

// ---------------- helpers ----------------
__device__ __forceinline__ uint32_t f2tf(float f) {
    uint32_t r;
    asm("cvt.rna.tf32.f32 %0, %1;" : "=r"(r) : "f"(f));
    return r;
}
__device__ __forceinline__ void cpa16(uint32_t d, const void* s) {
    asm volatile("cp.async.cg.shared.global [%0], [%1], 16;"
                 :: "r"(d), "l"(s));
}

// ---------------- weight prep: concat + tf32 convert ----------------
__global__ void prep_w_kernel(const float* __restrict__ Wl, const float* __restrict__ Wr,
                              uint32_t* __restrict__ Wc, int K, int Nh)
{
    int total = K * 2 * Nh;
    for (int idx = blockIdx.x * blockDim.x + threadIdx.x; idx < total;
         idx += gridDim.x * blockDim.x) {
        int k = idx / (2 * Nh);
        int c = idx % (2 * Nh);
        float v = (c < Nh) ? Wl[k * Nh + c] : Wr[k * Nh + (c - Nh)];
        Wc[idx] = f2tf(v);
    }
}

// ---------------- CSR build ----------------
__global__ void count_kernel(const int* __restrict__ edst)
{
    int idx = blockIdx.x * blockDim.x + threadIdx.x;
    if (idx >= ET) return;
    int d = (idx < EE) ? edst[idx] : idx - EE;
    atomicAdd(&g_deg[d], 1);
}

__global__ void scan_kernel()
{
    __shared__ int ssum[1024];
    int t = threadIdx.x;
    const int CH = (NN + 1023) / 1024;
    int lo = t * CH;
    int hi = min(lo + CH, NN);
    int s = 0;
    for (int i = lo; i < hi; i++) s += g_deg[i];
    ssum[t] = s;
    __syncthreads();
    for (int off = 1; off < 1024; off <<= 1) {
        int v = (t >= off) ? ssum[t - off] : 0;
        __syncthreads();
        ssum[t] += v;
        __syncthreads();
    }
    int base = (t == 0) ? 0 : ssum[t - 1];
    for (int i = lo; i < hi; i++) {
        g_rowptr[i] = base;
        g_cursor[i] = base;
        base += g_deg[i];
    }
    if (t == 0) g_rowptr[NN] = ET;
}

__global__ void scatter_kernel(const int* __restrict__ esrc, const int* __restrict__ edst)
{
    int idx = blockIdx.x * blockDim.x + threadIdx.x;
    if (idx >= ET) return;
    int s, d;
    if (idx < EE) { s = esrc[idx]; d = edst[idx]; }
    else          { s = d = idx - EE; }
    int pos = atomicAdd(&g_cursor[d], 1);
    g_csrsrc[pos] = s;
}

// ---------------- TF32 GEMM: cp.async staging; xl -> fp16 copy, xr -> fp32 ----------------
// Columns [0,Nh): xl, written as __half2 to Xh. Columns [Nh,2Nh): xr, fp32 to C.
__global__ __launch_bounds__(256, 2) void gemm_tf32_fused(
    const float* __restrict__ A, const uint32_t* __restrict__ Wc,
    const float* __restrict__ bl, const float* __restrict__ br,
    float* __restrict__ C, __half* __restrict__ Xh,
    int M, int K, int Nh)
{
    const int N = 2 * Nh;
    __shared__ float    As[2][128][20];
    __shared__ uint32_t Bs[2][16][136];
    int tid = threadIdx.x, lane = tid & 31, warp = tid >> 5;
    int wm = warp & 3, wn = warp >> 2;
    int rowBase = blockIdx.y * 128, colBase = blockIdx.x * 128;
    int grp = lane >> 2, tig = lane & 3;

    float acc[2][8][4];
    #pragma unroll
    for (int mt = 0; mt < 2; mt++)
        #pragma unroll
        for (int nt = 0; nt < 8; nt++)
            #pragma unroll
            for (int c = 0; c < 4; c++) acc[mt][nt][c] = 0.f;

    int nIter = K >> 4;
    int arow = tid >> 1;
    int akc  = (tid & 1) * 8;
    bool aok = (rowBase + arow) < M;
    const float* asrc = A + (size_t)(rowBase + arow) * K + akc;
    int brow = tid >> 4;
    int bcol = (tid & 15) * 8;
    bool bok0 = (colBase + bcol)     < N;
    bool bok1 = (colBase + bcol + 4) < N;
    const uint32_t* bsrc = Wc + (size_t)brow * N + colBase + bcol;

    {
        uint32_t da = (uint32_t)__cvta_generic_to_shared(&As[0][arow][akc]);
        if (aok) { cpa16(da, asrc); cpa16(da + 16, asrc + 4); }
        uint32_t db = (uint32_t)__cvta_generic_to_shared(&Bs[0][brow][bcol]);
        if (bok0) cpa16(db, bsrc);
        if (bok1) cpa16(db + 16, bsrc + 4);
    }
    asm volatile("cp.async.commit_group;");

    int buf = 0;
    for (int it = 0; it < nIter; it++) {
        asm volatile("cp.async.wait_group 0;");
        __syncthreads();
        bool more = (it + 1 < nIter);
        if (more) {
            int k0 = (it + 1) << 4;
            int b = buf ^ 1;
            uint32_t da = (uint32_t)__cvta_generic_to_shared(&As[b][arow][akc]);
            if (aok) { cpa16(da, asrc + k0); cpa16(da + 16, asrc + k0 + 4); }
            uint32_t db = (uint32_t)__cvta_generic_to_shared(&Bs[b][brow][bcol]);
            if (bok0) cpa16(db, bsrc + (size_t)k0 * N);
            if (bok1) cpa16(db + 16, bsrc + (size_t)k0 * N + 4);
            asm volatile("cp.async.commit_group;");
        }

        #pragma unroll
        for (int ks = 0; ks < 16; ks += 8) {
            uint32_t af[2][4], bf[8][2];
            #pragma unroll
            for (int mt = 0; mt < 2; mt++) {
                int m = wm * 32 + mt * 16;
                af[mt][0] = f2tf(As[buf][m + grp][ks + tig]);
                af[mt][1] = f2tf(As[buf][m + grp + 8][ks + tig]);
                af[mt][2] = f2tf(As[buf][m + grp][ks + tig + 4]);
                af[mt][3] = f2tf(As[buf][m + grp + 8][ks + tig + 4]);
            }
            #pragma unroll
            for (int nt = 0; nt < 8; nt++) {
                int nb = wn * 64 + nt * 8;
                bf[nt][0] = Bs[buf][ks + tig][nb + grp];
                bf[nt][1] = Bs[buf][ks + tig + 4][nb + grp];
            }
            #pragma unroll
            for (int mt = 0; mt < 2; mt++)
                #pragma unroll
                for (int nt = 0; nt < 8; nt++) {
                    asm volatile(
                        "mma.sync.aligned.m16n8k8.row.col.f32.tf32.tf32.f32 "
                        "{%0,%1,%2,%3}, {%4,%5,%6,%7}, {%8,%9}, {%0,%1,%2,%3};"
                        : "+f"(acc[mt][nt][0]), "+f"(acc[mt][nt][1]),
                          "+f"(acc[mt][nt][2]), "+f"(acc[mt][nt][3])
                        : "r"(af[mt][0]), "r"(af[mt][1]), "r"(af[mt][2]), "r"(af[mt][3]),
                          "r"(bf[nt][0]), "r"(bf[nt][1]));
                }
        }
        buf ^= 1;
    }

    // epilogue: xl -> half copy, xr -> fp32
    #pragma unroll
    for (int mt = 0; mt < 2; mt++) {
        #pragma unroll
        for (int nt = 0; nt < 8; nt++) {
            int row0 = rowBase + wm * 32 + mt * 16 + grp;
            int col0 = colBase + wn * 64 + nt * 8 + tig * 2;
            if (col0 < Nh) {
                float b0 = bl[col0], b1 = bl[col0 + 1];
                if (row0 < M) {
                    __half2 hv = __floats2half2_rn(acc[mt][nt][0] + b0, acc[mt][nt][1] + b1);
                    *(__half2*)(Xh + (size_t)row0 * Nh + col0) = hv;
                }
                if (row0 + 8 < M) {
                    __half2 hv = __floats2half2_rn(acc[mt][nt][2] + b0, acc[mt][nt][3] + b1);
                    *(__half2*)(Xh + (size_t)(row0 + 8) * Nh + col0) = hv;
                }
            } else if (col0 < N) {
                float b0 = br[col0 - Nh], b1 = br[col0 + 1 - Nh];
                if (row0 < M) {
                    float2 o = make_float2(acc[mt][nt][0] + b0, acc[mt][nt][1] + b1);
                    *(float2*)(C + (size_t)row0 * N + col0) = o;
                }
                if (row0 + 8 < M) {
                    float2 o = make_float2(acc[mt][nt][2] + b0, acc[mt][nt][3] + b1);
                    *(float2*)(C + (size_t)(row0 + 8) * N + col0) = o;
                }
            }
        }
    }
}

// ---------------- layer 1 agg: fp16 gather, warp/node, half-warp/edge, depth-2 ----------------
__global__ __launch_bounds__(256) void agg1_kernel(
    const float* __restrict__ xc, const __half* __restrict__ xlh,
    const int* __restrict__ rowptr, const int* __restrict__ csrsrc,
    const float* __restrict__ att, const float* __restrict__ bias,
    float* __restrict__ hout)
{
    int node = (blockIdx.x * blockDim.x + threadIdx.x) >> 5;
    int lane = threadIdx.x & 31;
    if (node >= NN) return;
    int sub = lane >> 4, l = lane & 15;

    const float* vp = xc + (size_t)node * 256 + 128 + l * 8;
    float4 vr0 = *(const float4*)(vp);
    float4 vr1 = *(const float4*)(vp + 4);
    float4 va0 = *(const float4*)(att + l * 8);
    float4 va1 = *(const float4*)(att + l * 8 + 4);

    int beg = rowptr[node], end = rowptr[node + 1];
    int iters = (end - beg + 1) >> 1;

    float4 acc0 = make_float4(0.f, 0.f, 0.f, 0.f);
    float4 acc1 = make_float4(0.f, 0.f, 0.f, 0.f);
    float ssum = 0.f;

    int idx = beg + sub;
    bool v = idx < end;
    int s = v ? csrsrc[idx] : csrsrc[beg];
    uint4 cu = *(const uint4*)(xlh + (size_t)s * F1 + l * 8);

    for (int it = 0; it < iters; it++) {
        int idxn = idx + 2;
        bool vn = idxn < end;
        int sn = vn ? csrsrc[idxn] : csrsrc[beg];
        uint4 nu = *(const uint4*)(xlh + (size_t)sn * F1 + l * 8);

        const __half2* hp = (const __half2*)&cu;
        float2 p0 = __half22float2(hp[0]);
        float2 p1 = __half22float2(hp[1]);
        float2 p2 = __half22float2(hp[2]);
        float2 p3 = __half22float2(hp[3]);

        float g, sum = 0.f;
        g = p0.x + vr0.x; g = g > 0.f ? g : SLOPE * g; sum += g * va0.x;
        g = p0.y + vr0.y; g = g > 0.f ? g : SLOPE * g; sum += g * va0.y;
        g = p1.x + vr0.z; g = g > 0.f ? g : SLOPE * g; sum += g * va0.z;
        g = p1.y + vr0.w; g = g > 0.f ? g : SLOPE * g; sum += g * va0.w;
        g = p2.x + vr1.x; g = g > 0.f ? g : SLOPE * g; sum += g * va1.x;
        g = p2.y + vr1.y; g = g > 0.f ? g : SLOPE * g; sum += g * va1.y;
        g = p3.x + vr1.z; g = g > 0.f ? g : SLOPE * g; sum += g * va1.z;
        g = p3.y + vr1.w; g = g > 0.f ? g : SLOPE * g; sum += g * va1.w;
        sum += __shfl_xor_sync(FULLMASK, sum, 1);
        sum += __shfl_xor_sync(FULLMASK, sum, 2);
        float a = v ? __expf(sum) : 0.f;
        acc0.x += a * p0.x; acc0.y += a * p0.y; acc0.z += a * p1.x; acc0.w += a * p1.y;
        acc1.x += a * p2.x; acc1.y += a * p2.y; acc1.z += a * p3.x; acc1.w += a * p3.y;
        ssum += a;
        cu = nu; v = vn; idx = idxn;
    }

    acc0.x += __shfl_xor_sync(FULLMASK, acc0.x, 16);
    acc0.y += __shfl_xor_sync(FULLMASK, acc0.y, 16);
    acc0.z += __shfl_xor_sync(FULLMASK, acc0.z, 16);
    acc0.w += __shfl_xor_sync(FULLMASK, acc0.w, 16);
    acc1.x += __shfl_xor_sync(FULLMASK, acc1.x, 16);
    acc1.y += __shfl_xor_sync(FULLMASK, acc1.y, 16);
    acc1.z += __shfl_xor_sync(FULLMASK, acc1.z, 16);
    acc1.w += __shfl_xor_sync(FULLMASK, acc1.w, 16);
    ssum   += __shfl_xor_sync(FULLMASK, ssum,   16);

    if (sub == 0) {
        float inv = 1.f / (ssum + 1e-16f);
        float4 b0 = *(const float4*)(bias + l * 8);
        float4 b1 = *(const float4*)(bias + l * 8 + 4);
        float4 o0, o1;
        o0.x = acc0.x * inv + b0.x; o0.y = acc0.y * inv + b0.y;
        o0.z = acc0.z * inv + b0.z; o0.w = acc0.w * inv + b0.w;
        o1.x = acc1.x * inv + b1.x; o1.y = acc1.y * inv + b1.y;
        o1.z = acc1.z * inv + b1.z; o1.w = acc1.w * inv + b1.w;
        o0.x = o0.x > 0.f ? o0.x : (__expf(o0.x) - 1.f);
        o0.y = o0.y > 0.f ? o0.y : (__expf(o0.y) - 1.f);
        o0.z = o0.z > 0.f ? o0.z : (__expf(o0.z) - 1.f);
        o0.w = o0.w > 0.f ? o0.w : (__expf(o0.w) - 1.f);
        o1.x = o1.x > 0.f ? o1.x : (__expf(o1.x) - 1.f);
        o1.y = o1.y > 0.f ? o1.y : (__expf(o1.y) - 1.f);
        o1.z = o1.z > 0.f ? o1.z : (__expf(o1.z) - 1.f);
        o1.w = o1.w > 0.f ? o1.w : (__expf(o1.w) - 1.f);
        *(float4*)(hout + (size_t)node * F1 + l * 8)     = o0;
        *(float4*)(hout + (size_t)node * F1 + l * 8 + 4) = o1;
    }
}

// ---------------- layer 2 agg: fp16 gather, warp/node, half-warp/edge, depth-2 ----------------
__global__ __launch_bounds__(256) void agg2_kernel(
    const float* __restrict__ xc, const __half* __restrict__ xlh,
    const int* __restrict__ rowptr, const int* __restrict__ csrsrc,
    const float* __restrict__ att, const float* __restrict__ bias,
    float* __restrict__ out)
{
    int node = (blockIdx.x * blockDim.x + threadIdx.x) >> 5;
    int lane = threadIdx.x & 31;
    if (node >= NN) return;
    int sub = lane >> 4, l = lane & 15;
    int base = l * 10;   // head = l>>2

    float2 vr[5], va[5];
    const float* vp = xc + (size_t)node * 320 + 160 + base;
    #pragma unroll
    for (int j = 0; j < 5; j++) {
        vr[j] = *(const float2*)(vp + 2 * j);
        va[j] = *(const float2*)(att + base + 2 * j);
    }

    int beg = rowptr[node], end = rowptr[node + 1];
    int iters = (end - beg + 1) >> 1;

    float2 acc[5];
    #pragma unroll
    for (int j = 0; j < 5; j++) acc[j] = make_float2(0.f, 0.f);
    float ssum = 0.f;

    int idx = beg + sub;
    bool v = idx < end;
    int s = v ? csrsrc[idx] : csrsrc[beg];
    uint32_t cu[5];
    {
        const __half* hb = xlh + (size_t)s * F2 + base;
        #pragma unroll
        for (int j = 0; j < 5; j++) cu[j] = *(const uint32_t*)(hb + 2 * j);
    }

    for (int it = 0; it < iters; it++) {
        int idxn = idx + 2;
        bool vn = idxn < end;
        int sn = vn ? csrsrc[idxn] : csrsrc[beg];
        uint32_t nu[5];
        {
            const __half* hb = xlh + (size_t)sn * F2 + base;
            #pragma unroll
            for (int j = 0; j < 5; j++) nu[j] = *(const uint32_t*)(hb + 2 * j);
        }
        float2 c[5];
        #pragma unroll
        for (int j = 0; j < 5; j++) c[j] = __half22float2(*(const __half2*)&cu[j]);

        float sum = 0.f;
        #pragma unroll
        for (int j = 0; j < 5; j++) {
            float g = c[j].x + vr[j].x; g = g > 0.f ? g : SLOPE * g; sum += g * va[j].x;
            g       = c[j].y + vr[j].y; g = g > 0.f ? g : SLOPE * g; sum += g * va[j].y;
        }
        sum += __shfl_xor_sync(FULLMASK, sum, 1);
        sum += __shfl_xor_sync(FULLMASK, sum, 2);
        float a = v ? __expf(sum) : 0.f;
        #pragma unroll
        for (int j = 0; j < 5; j++) { acc[j].x += a * c[j].x; acc[j].y += a * c[j].y; }
        ssum += a;
        #pragma unroll
        for (int j = 0; j < 5; j++) cu[j] = nu[j];
        v = vn; idx = idxn;
    }

    #pragma unroll
    for (int j = 0; j < 5; j++) {
        acc[j].x += __shfl_xor_sync(FULLMASK, acc[j].x, 16);
        acc[j].y += __shfl_xor_sync(FULLMASK, acc[j].y, 16);
    }
    ssum += __shfl_xor_sync(FULLMASK, ssum, 16);

    float inv = 1.f / (ssum + 1e-16f);
    #pragma unroll
    for (int j = 0; j < 5; j++) {
        float vx = acc[j].x * inv, vy = acc[j].y * inv;
        vx += __shfl_xor_sync(FULLMASK, vx, 4);
        vx += __shfl_xor_sync(FULLMASK, vx, 8);
        vy += __shfl_xor_sync(FULLMASK, vy, 4);
        vy += __shfl_xor_sync(FULLMASK, vy, 8);
        acc[j].x = vx; acc[j].y = vy;
    }

    if (sub == 0 && l < 4) {
        #pragma unroll
        for (int j = 0; j < 5; j++) {
            float2 o;
            o.x = 0.25f * acc[j].x + bias[base + 2 * j];
            o.y = 0.25f * acc[j].y + bias[base + 2 * j + 1];
            *(float2*)(out + (size_t)node * OUT_DIM + base + 2 * j) = o;
        }
    }
}

// ---------------- host ----------------
struct Ptrs {
    float *xc1, *xc2, *h;
    __half *xlh1, *xlh2;
    uint32_t *Wc1, *Wc2;
    int *deg, *rowptr, *csrsrc;
};
static Ptrs P;
static cudaStream_t g_s2;
static cudaEvent_t g_ev1, g_ev2;
static bool g_init = false;

extern "C" void kernel_launch(void* const* d_in, const int* in_sizes, int n_in,
                              void* d_out, int out_size)
{
    if (!g_init) {
        cudaGetSymbolAddress((void**)&P.xc1,    g_xc1);
        cudaGetSymbolAddress((void**)&P.xc2,    g_xc2);
        cudaGetSymbolAddress((void**)&P.xlh1,   g_xlh1);
        cudaGetSymbolAddress((void**)&P.xlh2,   g_xlh2);
        cudaGetSymbolAddress((void**)&P.h,      g_h);
        cudaGetSymbolAddress((void**)&P.Wc1,    g_Wc1);
        cudaGetSymbolAddress((void**)&P.Wc2,    g_Wc2);
        cudaGetSymbolAddress((void**)&P.deg,    g_deg);
        cudaGetSymbolAddress((void**)&P.rowptr, g_rowptr);
        cudaGetSymbolAddress((void**)&P.csrsrc, g_csrsrc);
        cudaStreamCreateWithFlags(&g_s2, cudaStreamNonBlocking);
        cudaEventCreateWithFlags(&g_ev1, cudaEventDisableTiming);
        cudaEventCreateWithFlags(&g_ev2, cudaEventDisableTiming);
        g_init = true;
    }

    const float* x     = (const float*)d_in[0];
    const int*   ei    = (const int*)  d_in[1];
    const float* Wl1   = (const float*)d_in[2];
    const float* bl1   = (const float*)d_in[3];
    const float* Wr1   = (const float*)d_in[4];
    const float* br1   = (const float*)d_in[5];
    const float* att1  = (const float*)d_in[6];
    const float* bias1 = (const float*)d_in[7];
    const float* Wl2   = (const float*)d_in[8];
    const float* bl2   = (const float*)d_in[9];
    const float* Wr2   = (const float*)d_in[10];
    const float* br2   = (const float*)d_in[11];
    const float* att2  = (const float*)d_in[12];
    const float* bias2 = (const float*)d_in[13];
    float* out = (float*)d_out;

    const int* esrc = ei;
    const int* edst = ei + EE;

    // fork: CSR build + prep2 on side stream, concurrent with prep1+GEMM1
    cudaEventRecord(g_ev1, 0);
    cudaStreamWaitEvent(g_s2, g_ev1, 0);
    cudaMemsetAsync(P.deg, 0, NN * sizeof(int), g_s2);
    count_kernel<<<(ET + 255) / 256, 256, 0, g_s2>>>(edst);
    scan_kernel<<<1, 1024, 0, g_s2>>>();
    scatter_kernel<<<(ET + 255) / 256, 256, 0, g_s2>>>(esrc, edst);
    prep_w_kernel<<<128, 256, 0, g_s2>>>(Wl2, Wr2, P.Wc2, F1, F2);
    cudaEventRecord(g_ev2, g_s2);

    // ----- layer 1: prep + GEMM (main stream) -----
    prep_w_kernel<<<128, 256>>>(Wl1, Wr1, P.Wc1, IN_DIM, F1);
    {
        dim3 grid(2, (NN + 127) / 128);
        gemm_tf32_fused<<<grid, 256>>>(x, P.Wc1, bl1, br1, P.xc1, P.xlh1, NN, IN_DIM, F1);
    }
    cudaStreamWaitEvent(0, g_ev2, 0);
    agg1_kernel<<<(NN * 32 + 255) / 256, 256>>>(P.xc1, P.xlh1, P.rowptr, P.csrsrc,
                                                att1, bias1, P.h);

    // ----- layer 2 -----
    {
        dim3 grid(3, (NN + 127) / 128);
        gemm_tf32_fused<<<grid, 256>>>(P.h, P.Wc2, bl2, br2, P.xc2, P.xlh2, NN, F1, F2);
    }
    agg2_kernel<<<(NN * 32 + 255) / 256, 256>>>(P.xc2, P.xlh2, P.rowptr, P.csrsrc,
                                                att2, bias2, out);
}